// round 13
// baseline (speedup 1.0000x reference)
#include <cuda_runtime.h>

#define BB 32
#define PP 65536
#define TT 16
#define NB 2048
#define BLK 256
#define IPT 16
#define NBLK (PP/(BLK*IPT))   // 16 blocks per batch in k1
#define IPTF 16
#define NBLKF (PP/(256*IPTF)) // 16 blocks per batch in filters
#define SEEDN 8192
#define GMARGIN 1.000002f

// ---------------- device scratch ----------------
__device__ unsigned int       g_mine[BB][PP];
__device__ unsigned long long g_skey[BB][TT];
__device__ int    g_cand[BB][PP];
__device__ int    g_ccnt[BB];
__device__ int    g_pos[BB][PP];
__device__ int    g_pcnt[BB];
__device__ int    g_h1c[BB][NB];
__device__ int    g_h2c[BB][NB];
__device__ int    g_h3c[BB][NB];
__device__ int    g_poscnt[BB];
__device__ double g_posloss[BB];
__device__ double g_lossl;
__device__ unsigned g_pref0[BB];
__device__ int    g_R1[BB];
__device__ unsigned g_pref22[BB];
__device__ int    g_R2[BB];
__device__ double g_sgt[BB];
__device__ double g_topsum[BB];
__device__ int    g_ctr;

// ---------------- helpers (bit-identical across kernels) ----------------
struct Box { float x0, y0, x1, y1, areaB; };

__device__ __forceinline__ Box mkbox(float4 pr) {
    Box b;
    float hx = __fmul_rn(0.5f, pr.z), hy = __fmul_rn(0.5f, pr.w);
    b.x0 = __fsub_rn(pr.x, hx); b.y0 = __fsub_rn(pr.y, hy);
    b.x1 = __fadd_rn(pr.x, hx); b.y1 = __fadd_rn(pr.y, hy);
    b.areaB = __fmul_rn(__fsub_rn(b.x1, b.x0), __fsub_rn(b.y1, b.y0));
    return b;
}

__device__ __forceinline__ void iou_id(const Box& bx, float4 a, float ca,
                                       float& inter, float& den) {
    float w = fmaxf(__fsub_rn(fminf(a.z, bx.x1), fmaxf(a.x, bx.x0)), 0.0f);
    float h = fmaxf(__fsub_rn(fminf(a.w, bx.y1), fmaxf(a.y, bx.y0)), 0.0f);
    inter = __fmul_rn(w, h);
    den = __fsub_rn(__fadd_rn(ca, bx.areaB), inter);
}

// Serial chain argmax, (bi,bd) only — fp sequence identical to match_idx.
__device__ __forceinline__ void match_val(
    const Box& bx, const float4* tr, const float* cA, float& bi, float& bd)
{
    bi = -1.0f; bd = 1.0f;
#pragma unroll
    for (int t = 0; t < TT; t++) {
        float inter, den;
        iou_id(bx, tr[t], cA[t], inter, den);
        if (__fmul_rn(inter, bd) > __fmul_rn(bi, den)) { bi = inter; bd = den; }
    }
}

// Same chain with index tracking (used only off the hot path).
__device__ __forceinline__ void match_idx(
    const Box& bx, const float4* tr, const float* cA,
    float& bi, float& bd, int& bti)
{
    bi = -1.0f; bd = 1.0f; bti = 0;
#pragma unroll
    for (int t = 0; t < TT; t++) {
        float inter, den;
        iou_id(bx, tr[t], cA[t], inter, den);
        if (__fmul_rn(inter, bd) > __fmul_rn(bi, den)) { bi = inter; bd = den; bti = t; }
    }
}

__device__ __forceinline__ float lse2(float2 c) {
    return __fadd_rn(fmaxf(c.x, c.y),
                     __logf(__fadd_rn(1.0f, __expf(-fabsf(__fsub_rn(c.x, c.y))))));
}

__device__ __forceinline__ float loc_sl1(float4 ld, float4 a, float4 pr) {
    float gx = ((a.x + a.z) * 0.5f - pr.x) / (0.1f * pr.z);
    float gy = ((a.y + a.w) * 0.5f - pr.y) / (0.1f * pr.w);
    float gw = __logf((a.z - a.x) / pr.z) / 0.2f;
    float gh = __logf((a.w - a.y) / pr.w) / 0.2f;
    float d0 = fabsf(ld.x - gx), d1 = fabsf(ld.y - gy);
    float d2 = fabsf(ld.z - gw), d3 = fabsf(ld.w - gh);
    return (d0 < 1.f ? 0.5f * d0 * d0 : d0 - 0.5f)
         + (d1 < 1.f ? 0.5f * d1 * d1 : d1 - 0.5f)
         + (d2 < 1.f ? 0.5f * d2 * d2 : d2 - 0.5f)
         + (d3 < 1.f ? 0.5f * d3 * d3 : d3 - 0.5f);
}

// warp-aggregated list append; returns nothing.
__device__ __forceinline__ void list_append(int* list, int* cnt, bool flag, int p,
                                            int lane) {
    unsigned m = __ballot_sync(0xFFFFFFFFu, flag);
    if (m) {
        int leader = __ffs(m) - 1;
        int base;
        if (lane == leader) base = atomicAdd(cnt, __popc(m));
        base = __shfl_sync(0xFFFFFFFFu, base, leader);
        if (flag) list[base + __popc(m & ((1u << lane) - 1u))] = p;
    }
}

// Parallel descending radix-select over NB bins.
__device__ __forceinline__ void scan_desc(const int* cnt, int R, int tid,
                                          int* s_w, unsigned* s_idx, int* s_rem,
                                          int* lc_out)
{
    int lane = tid & 31, w = tid >> 5;
    int base = tid * 8;
    int c = 0;
#pragma unroll
    for (int k = 0; k < 8; k++) { lc_out[k] = cnt[NB - 1 - (base + k)]; c += lc_out[k]; }
    int inc = c;
#pragma unroll
    for (int o = 1; o < 32; o <<= 1) {
        int n = __shfl_up_sync(0xFFFFFFFFu, inc, o);
        if (lane >= o) inc += n;
    }
    if (lane == 31) s_w[w] = inc;
    __syncthreads();
    if (tid == 0) {
        int rc = 0;
        for (int i = 0; i < 8; i++) { int v = s_w[i]; s_w[i] = rc; rc += v; }
    }
    __syncthreads();
    int epc = s_w[w] + inc - c;
    if (epc < R && R <= epc + c) {
        int rc = epc;
#pragma unroll
        for (int k = 0; k < 8; k++) {
            int idx = NB - 1 - (base + k);
            if (rc + lc_out[k] >= R) { *s_idx = (unsigned)idx; *s_rem = R - rc; break; }
            rc += lc_out[k];
        }
    }
    __syncthreads();
}

// ---------------- K0: zero accumulators ----------------
__global__ void __launch_bounds__(256) k_zero() {
    int g = blockIdx.x * 256 + threadIdx.x;
    for (int i = g; i < BB * NB; i += 16384) {
        ((int*)g_h1c)[i] = 0;
        ((int*)g_h2c)[i] = 0;
        ((int*)g_h3c)[i] = 0;
    }
    if (g < BB) {
        g_poscnt[g] = 0; g_posloss[g] = 0.0; g_sgt[g] = 0.0;
        g_ccnt[g] = 0; g_pcnt[g] = 0;
    }
    if (g == BB) { g_lossl = 0.0; g_ctr = 0; }
}

// ---------------- kseed: warp-per-truth over first SEEDN priors ----------------
__global__ void __launch_bounds__(256) kseed(const float4* __restrict__ priors,
                                             const float*  __restrict__ targets,
                                             int half) {
    int b = blockIdx.x, tid = threadIdx.x, w = tid >> 5, lane = tid & 31;
    int t = half * 8 + w;
    const float* tb = targets + (b * TT + t) * 5;
    float4 a = make_float4(tb[0], tb[1], tb[2], tb[3]);
    float ca = __fmul_rn(__fsub_rn(a.z, a.x), __fsub_rn(a.w, a.y));
    float bi = -1.0f, bd = 1.0f; unsigned bp = 0;
#pragma unroll 4
    for (int i = 0; i < SEEDN; i += 32) {
        int p = i + lane;
        Box bx = mkbox(priors[p]);
        float inter, den;
        iou_id(bx, a, ca, inter, den);
        if (__fmul_rn(inter, bd) > __fmul_rn(bi, den)) { bi = inter; bd = den; bp = p; }
    }
#pragma unroll
    for (int o = 16; o > 0; o >>= 1) {
        float oi = __shfl_down_sync(0xFFFFFFFFu, bi, o);
        float od = __shfl_down_sync(0xFFFFFFFFu, bd, o);
        unsigned op_ = __shfl_down_sync(0xFFFFFFFFu, bp, o);
        if (__fmul_rn(oi, bd) > __fmul_rn(bi, od)) { bi = oi; bd = od; bp = op_; }
    }
    if (lane == 0) {
        float iou = __fdiv_rn(bi, bd);
        g_skey[b][t] = ((unsigned long long)__float_as_uint(iou) << 32)
                     | (unsigned long long)(0xFFFFFFFFu - bp);   // exclusive owner
    }
}

// ---------------- K1: slim — chain(bi,bd) + lse + mine + hist + two appends ----------------
__global__ void __launch_bounds__(BLK, 3) k1(const float2* __restrict__ conf,
                                             const float4* __restrict__ priors,
                                             const float*  __restrict__ targets) {
    int b = blockIdx.y, tid = threadIdx.x, lane = tid & 31;
    __shared__ float4 tr[TT];
    __shared__ float  cA[TT];
    __shared__ int    sc[NB];
    for (int i = tid; i < NB; i += BLK) sc[i] = 0;
    if (tid < TT) {
        const float* tb = targets + (b * TT + tid) * 5;
        float4 v = make_float4(tb[0], tb[1], tb[2], tb[3]);
        tr[tid] = v;
        cA[tid] = __fmul_rn(__fsub_rn(v.z, v.x), __fsub_rn(v.w, v.y));
    }
    __syncthreads();

    float c_min = 1e30f;
#pragma unroll
    for (int t = 0; t < TT; t++)
        c_min = fminf(c_min, __uint_as_float((unsigned)(g_skey[b][t] >> 32)));

    float ploss = 0.0f;
    int pcnt = 0;
    int pbase = blockIdx.x * (BLK * IPT);
#pragma unroll 1
    for (int i = 0; i < IPT; i++) {
        int p = pbase + i * BLK + tid;
        float4 pr = priors[p];
        Box bx = mkbox(pr);
        float bi, bd;
        match_val(bx, tr, cA, bi, bd);

        bool maybe = (__fmul_rn(bi, GMARGIN) >= __fmul_rn(c_min, bd));
        list_append(g_cand[b], &g_ccnt[b], maybe, p, lane);

        bool pos = (__fmul_rn(2.0f, bi) >= bd);
        list_append(g_pos[b], &g_pcnt[b], pos, p, lane);

        float2 c = conf[(size_t)b * PP + p];
        float lse = lse2(c);
        float mv = pos ? 0.0f : __fsub_rn(lse, c.x);
        unsigned bits = __float_as_uint(mv);
        g_mine[b][p] = bits;
        unsigned bin = bits >> 21;
        unsigned peers = __match_any_sync(0xFFFFFFFFu, bin);
        if (lane == __ffs(peers) - 1) atomicAdd(&sc[bin], __popc(peers));
        if (pos) { pcnt++; ploss += __fsub_rn(lse, c.y); }
    }

#pragma unroll
    for (int o = 16; o > 0; o >>= 1) {
        ploss += __shfl_down_sync(0xFFFFFFFFu, ploss, o);
        pcnt  += __shfl_down_sync(0xFFFFFFFFu, pcnt, o);
    }
    if (lane == 0 && pcnt) {
        atomicAdd(&g_poscnt[b], pcnt);
        atomicAdd(&g_posloss[b], (double)ploss);
    }
    __syncthreads();
    for (int i = tid; i < NB; i += BLK) {
        int cv = sc[i];
        if (cv) atomicAdd(&g_h1c[b][i], cv);
    }
}

// ---------------- k_cand: replay gate candidates, exact per-truth argmax ----------------
__global__ void __launch_bounds__(256) k_cand(const float4* __restrict__ priors,
                                              const float*  __restrict__ targets) {
    int b = blockIdx.x, tid = threadIdx.x;
    __shared__ float4 tr[TT];
    __shared__ float  cA[TT];
    __shared__ float  s_ct[TT];
    if (tid < TT) {
        const float* tb = targets + (b * TT + tid) * 5;
        float4 v = make_float4(tb[0], tb[1], tb[2], tb[3]);
        tr[tid] = v;
        cA[tid] = __fmul_rn(__fsub_rn(v.z, v.x), __fsub_rn(v.w, v.y));
        s_ct[tid] = __uint_as_float((unsigned)(g_skey[b][tid] >> 32));
    }
    __syncthreads();

    int n = g_ccnt[b];
    for (int i = blockIdx.y * 256 + tid; i < n; i += 8 * 256) {
        int p = g_cand[b][i];
        Box bx = mkbox(priors[p]);
#pragma unroll
        for (int t = 0; t < TT; t++) {
            float inter, den;
            iou_id(bx, tr[t], cA[t], inter, den);
            if (__fmul_rn(inter, GMARGIN) >= __fmul_rn(s_ct[t], den)) {
                float iou = __fdiv_rn(inter, den);
                unsigned long long key =
                    ((unsigned long long)__float_as_uint(iou) << 32) |
                    (unsigned long long)(0xFFFFFFFFu - (unsigned)p);
                atomicMax(&g_skey[b][t], key);
            }
        }
    }
}

// ---------------- k_pos: smooth-L1 for positives (recomputes argmax index) ----------------
__global__ void __launch_bounds__(256) k_pos(const float4* __restrict__ loc,
                                             const float4* __restrict__ priors,
                                             const float*  __restrict__ targets) {
    int b = blockIdx.x, tid = threadIdx.x, lane = tid & 31;
    __shared__ float4 tr[TT];
    __shared__ float  cA[TT];
    if (tid < TT) {
        const float* tb = targets + (b * TT + tid) * 5;
        float4 v = make_float4(tb[0], tb[1], tb[2], tb[3]);
        tr[tid] = v;
        cA[tid] = __fmul_rn(__fsub_rn(v.z, v.x), __fsub_rn(v.w, v.y));
    }
    __syncthreads();

    int n = g_pcnt[b];
    float lossl = 0.0f;
    for (int i = blockIdx.y * 256 + tid; i < n; i += 8 * 256) {
        int p = g_pos[b][i];
        float4 pr = priors[p];
        Box bx = mkbox(pr);
        float bi, bd; int bti;
        match_idx(bx, tr, cA, bi, bd, bti);
        lossl += loc_sl1(loc[(size_t)b * PP + p], tr[bti], pr);
    }
#pragma unroll
    for (int o = 16; o > 0; o >>= 1)
        lossl += __shfl_down_sync(0xFFFFFFFFu, lossl, o);
    if (lane == 0 && lossl != 0.0f) atomicAdd(&g_lossl, (double)lossl);
}

// ---------------- K2: best-prior override fixup — thread per (b,t) ----------------
__global__ void __launch_bounds__(512) k_fix(const float4* __restrict__ loc,
                                             const float2* __restrict__ conf,
                                             const float4* __restrict__ priors,
                                             const float*  __restrict__ targets) {
    int tid = threadIdx.x;
    int b = tid >> 4, t = tid & 15;
    __shared__ float4   str[BB][TT];
    __shared__ float    scA[BB][TT];
    __shared__ unsigned sps[BB][TT];
    {
        const float* tb = targets + (b * TT + t) * 5;
        float4 v = make_float4(tb[0], tb[1], tb[2], tb[3]);
        str[b][t] = v;
        scA[b][t] = __fmul_rn(__fsub_rn(v.z, v.x), __fsub_rn(v.w, v.y));
        sps[b][t] = 0xFFFFFFFFu - (unsigned)(g_skey[b][t] & 0xFFFFFFFFull);
    }
    __syncthreads();

    unsigned p = sps[b][t];
    bool last = true;
#pragma unroll
    for (int t2 = 0; t2 < TT; t2++)
        if (t2 > t && sps[b][t2] == p) last = false;
    if (!last) return;                       // last write wins

    float4 pr = priors[p];
    Box bx = mkbox(pr);
    float bi, bd; int bti;
    match_idx(bx, str[b], scA[b], bi, bd, bti);
    bool pos_old = (__fmul_rn(2.0f, bi) >= bd);
    float2 c = conf[(size_t)b * PP + p];
    float lse = lse2(c);
    float4 ld = loc[(size_t)b * PP + p];
    float sl_new = loc_sl1(ld, str[b][t], pr);
    double dl = 0.0;
    if (pos_old) {
        if (bti != t) dl = (double)sl_new - (double)loc_sl1(ld, str[b][bti], pr);
    } else {
        dl = (double)sl_new;
        atomicAdd(&g_poscnt[b], 1);
        atomicAdd(&g_posloss[b], (double)__fsub_rn(lse, c.y));
        float mo = __fsub_rn(lse, c.x);      // bit-identical to k1's mv
        unsigned ob = __float_as_uint(mo) >> 21;
        atomicSub(&g_h1c[b][ob], 1);
        atomicAdd(&g_h1c[b][0], 1);
        g_mine[b][p] = 0u;
    }
    if (dl != 0.0) atomicAdd(&g_lossl, dl);
}

// ---------------- k_fa: in-block level-0 select + level-1 histogram ----------------
__global__ void __launch_bounds__(256) k_fa() {
    int b = blockIdx.y, tid = threadIdx.x;
    __shared__ int sc[NB];
    __shared__ int s_w[8];
    __shared__ unsigned s_idx;
    __shared__ int s_rem;
    for (int i = tid; i < NB; i += 256) sc[i] = 0;

    int k3 = 3 * g_poscnt[b];
    int R = (k3 < PP - 1) ? k3 : (PP - 1);
    int lc[8];
    scan_desc(g_h1c[b], R, tid, s_w, &s_idx, &s_rem, lc);
    unsigned pref = s_idx;

    const uint4* mp = (const uint4*)&g_mine[b][0];
    int base = blockIdx.x * (PP / 4 / NBLKF);
#pragma unroll 4
    for (int i = tid; i < PP / 4 / NBLKF; i += 256) {
        uint4 v = mp[base + i];
        if ((v.x >> 21) == pref) atomicAdd(&sc[(v.x >> 10) & 0x7FFu], 1);
        if ((v.y >> 21) == pref) atomicAdd(&sc[(v.y >> 10) & 0x7FFu], 1);
        if ((v.z >> 21) == pref) atomicAdd(&sc[(v.z >> 10) & 0x7FFu], 1);
        if ((v.w >> 21) == pref) atomicAdd(&sc[(v.w >> 10) & 0x7FFu], 1);
    }
    __syncthreads();
    for (int i = tid; i < NB; i += 256)
        if (sc[i]) atomicAdd(&g_h2c[b][i], sc[i]);
    if (tid == 0 && blockIdx.x == 0) { g_pref0[b] = pref; g_R1[b] = s_rem; }
}

// ---------------- k_fb: in-block level-1 select + level-2 hist + upper sum ----------------
__global__ void __launch_bounds__(256) k_fb() {
    int b = blockIdx.y, tid = threadIdx.x, lane = tid & 31;
    __shared__ int sc[NB];
    __shared__ int s_w[8];
    __shared__ unsigned s_idx;
    __shared__ int s_rem;
    for (int i = tid; i < NB; i += 256) sc[i] = 0;

    int lc[8];
    scan_desc(g_h2c[b], g_R1[b], tid, s_w, &s_idx, &s_rem, lc);
    unsigned pref22 = (g_pref0[b] << 11) | s_idx;

    double fsum = 0.0;
    const uint4* mp = (const uint4*)&g_mine[b][0];
    int base = blockIdx.x * (PP / 4 / NBLKF);
#pragma unroll 4
    for (int i = tid; i < PP / 4 / NBLKF; i += 256) {
        uint4 v = mp[base + i];
        unsigned t0 = v.x >> 10, t1 = v.y >> 10, t2 = v.z >> 10, t3 = v.w >> 10;
        if (t0 == pref22) atomicAdd(&sc[v.x & 0x3FFu], 1);
        else if (t0 > pref22) fsum += (double)__uint_as_float(v.x);
        if (t1 == pref22) atomicAdd(&sc[v.y & 0x3FFu], 1);
        else if (t1 > pref22) fsum += (double)__uint_as_float(v.y);
        if (t2 == pref22) atomicAdd(&sc[v.z & 0x3FFu], 1);
        else if (t2 > pref22) fsum += (double)__uint_as_float(v.z);
        if (t3 == pref22) atomicAdd(&sc[v.w & 0x3FFu], 1);
        else if (t3 > pref22) fsum += (double)__uint_as_float(v.w);
    }
    __syncthreads();
    for (int i = tid; i < NB; i += 256)
        if (sc[i]) atomicAdd(&g_h3c[b][i], sc[i]);
#pragma unroll
    for (int o = 16; o > 0; o >>= 1)
        fsum += __shfl_down_sync(0xFFFFFFFFu, fsum, o);
    if (lane == 0 && fsum != 0.0) atomicAdd(&g_sgt[b], fsum);
    if (tid == 0 && blockIdx.x == 0) { g_pref22[b] = pref22; g_R2[b] = s_rem; }
}

// ---------------- k_last: level-2 select + exact top-K sum + final combine ----------------
__global__ void __launch_bounds__(256) k_last(float* __restrict__ out) {
    int b = blockIdx.x, tid = threadIdx.x;
    __shared__ int s_w[8];
    __shared__ unsigned s_idx;
    __shared__ int s_rem;
    __shared__ double s_ws[8];
    __shared__ int s_last;

    int lc[8];
    scan_desc(g_h3c[b], g_R2[b], tid, s_w, &s_idx, &s_rem, lc);
    unsigned pref = g_pref22[b];
    unsigned idx3 = s_idx;
    int R3 = s_rem;

    double s = 0.0;
    int base = tid * 8;
#pragma unroll
    for (int k = 0; k < 8; k++) {
        unsigned idx = (unsigned)(NB - 1 - (base + k));
        if (idx > idx3 && lc[k])
            s += (double)lc[k] * (double)__uint_as_float((pref << 10) | idx);
    }
#pragma unroll
    for (int o = 16; o > 0; o >>= 1)
        s += __shfl_down_sync(0xFFFFFFFFu, s, o);
    if ((tid & 31) == 0) s_ws[tid >> 5] = s;
    __syncthreads();
    if (tid == 0) {
        double tot = 0.0;
        for (int w = 0; w < 8; w++) tot += s_ws[w];
        g_topsum[b] = g_sgt[b] + tot +
                      (double)R3 * (double)__uint_as_float((pref << 10) | idx3);
        __threadfence();
        int done = atomicAdd(&g_ctr, 1);
        s_last = (done == BB - 1) ? 1 : 0;
    }
    __syncthreads();
    if (s_last) {
        __threadfence();
        if (tid < 32) {
            int np = g_poscnt[tid];
            double lc2 = g_posloss[tid] + g_topsum[tid];
#pragma unroll
            for (int o = 16; o > 0; o >>= 1) {
                np  += __shfl_down_sync(0xFFFFFFFFu, np, o);
                lc2 += __shfl_down_sync(0xFFFFFFFFu, lc2, o);
            }
            if (tid == 0) {
                double N = (double)np;
                out[0] = (float)(g_lossl / N);
                out[1] = (float)(lc2 / N);
            }
        }
    }
}

// ---------------- launch ----------------
extern "C" void kernel_launch(void* const* d_in, const int* in_sizes, int n_in,
                              void* d_out, int out_size) {
    const float4* loc     = (const float4*)d_in[0];
    const float2* conf    = (const float2*)d_in[1];
    const float4* priors  = (const float4*)d_in[2];
    const float*  targets = (const float*)d_in[3];
    float* out = (float*)d_out;

    k_zero<<<64, 256>>>();                              // 1
    kseed<<<BB, 256>>>(priors, targets, 0);             // 2
    kseed<<<BB, 256>>>(priors, targets, 1);             // 3
    dim3 g1(NBLK, BB);
    k1<<<g1, BLK>>>(conf, priors, targets);             // 4 -> ncu captures this
    dim3 g8(BB, 8);
    k_cand<<<g8, 256>>>(priors, targets);               // 5
    k_pos<<<g8, 256>>>(loc, priors, targets);           // 6
    k_fix<<<1, 512>>>(loc, conf, priors, targets);      // 7
    dim3 gf(NBLKF, BB);
    k_fa<<<gf, 256>>>();                                // 8
    k_fb<<<gf, 256>>>();                                // 9
    k_last<<<BB, 256>>>(out);                           // 10
}

// round 14
// speedup vs baseline: 1.8102x; 1.8102x over previous
#include <cuda_runtime.h>

#define BB 32
#define PP 65536
#define TT 16
#define NB 2048
#define BLK 256
#define IPT 16
#define NBLK (PP/(BLK*IPT))   // 16 blocks per batch in k1
#define NBLKF 32              // 32 blocks per batch in filters
#define SEEDN 8192
#define GMARGIN 1.000002f

// ---------------- device scratch ----------------
__device__ unsigned int       g_mine[BB][PP];
__device__ unsigned long long g_skey[BB][TT];
__device__ unsigned short     g_tmask[BB][1024];
__device__ int    g_mhx;      // float bits of max prior half-width (persistent, idempotent)
__device__ int    g_mhy;
__device__ int    g_h1c[BB][NB];
__device__ int    g_h2c[BB][NB];
__device__ int    g_h3c[BB][NB];
__device__ int    g_poscnt[BB];
__device__ double g_posloss[BB];
__device__ double g_lossl;
__device__ unsigned g_pref0[BB];
__device__ int    g_R1[BB];
__device__ unsigned g_pref22[BB];
__device__ int    g_R2[BB];
__device__ double g_sgt[BB];
__device__ double g_topsum[BB];
__device__ int    g_ctr;

// ---------------- helpers (bit-identical across kernels) ----------------
struct Box { float x0, y0, x1, y1, areaB; };

__device__ __forceinline__ Box mkbox(float4 pr) {
    Box b;
    float hx = __fmul_rn(0.5f, pr.z), hy = __fmul_rn(0.5f, pr.w);
    b.x0 = __fsub_rn(pr.x, hx); b.y0 = __fsub_rn(pr.y, hy);
    b.x1 = __fadd_rn(pr.x, hx); b.y1 = __fadd_rn(pr.y, hy);
    b.areaB = __fmul_rn(__fsub_rn(b.x1, b.x0), __fsub_rn(b.y1, b.y0));
    return b;
}

__device__ __forceinline__ void iou_id(const Box& bx, float4 a, float ca,
                                       float& inter, float& den) {
    float w = fmaxf(__fsub_rn(fminf(a.z, bx.x1), fmaxf(a.x, bx.x0)), 0.0f);
    float h = fmaxf(__fsub_rn(fminf(a.w, bx.y1), fmaxf(a.y, bx.y0)), 0.0f);
    inter = __fmul_rn(w, h);
    den = __fsub_rn(__fadd_rn(ca, bx.areaB), inter);
}

// Full serial chain argmax (used off the hot path: k_fix).
__device__ __forceinline__ void match_idx(
    const Box& bx, const float4* tr, const float* cA,
    float& bi, float& bd, int& bti)
{
    bi = -1.0f; bd = 1.0f; bti = 0;
#pragma unroll
    for (int t = 0; t < TT; t++) {
        float inter, den;
        iou_id(bx, tr[t], cA[t], inter, den);
        if (__fmul_rn(inter, bd) > __fmul_rn(bi, den)) { bi = inter; bd = den; bti = t; }
    }
}

__device__ __forceinline__ float lse2(float2 c) {
    return __fadd_rn(fmaxf(c.x, c.y),
                     __logf(__fadd_rn(1.0f, __expf(-fabsf(__fsub_rn(c.x, c.y))))));
}

__device__ __forceinline__ float loc_sl1(float4 ld, float4 a, float4 pr) {
    float gx = ((a.x + a.z) * 0.5f - pr.x) / (0.1f * pr.z);
    float gy = ((a.y + a.w) * 0.5f - pr.y) / (0.1f * pr.w);
    float gw = __logf((a.z - a.x) / pr.z) / 0.2f;
    float gh = __logf((a.w - a.y) / pr.w) / 0.2f;
    float d0 = fabsf(ld.x - gx), d1 = fabsf(ld.y - gy);
    float d2 = fabsf(ld.z - gw), d3 = fabsf(ld.w - gh);
    return (d0 < 1.f ? 0.5f * d0 * d0 : d0 - 0.5f)
         + (d1 < 1.f ? 0.5f * d1 * d1 : d1 - 0.5f)
         + (d2 < 1.f ? 0.5f * d2 * d2 : d2 - 0.5f)
         + (d3 < 1.f ? 0.5f * d3 * d3 : d3 - 0.5f);
}

// Parallel descending radix-select over NB bins; cnt may be global or shared.
__device__ __forceinline__ void scan_desc(const int* cnt, int R, int tid,
                                          int* s_w, unsigned* s_idx, int* s_rem,
                                          int* lc_out)
{
    int lane = tid & 31, w = tid >> 5;
    int base = tid * 8;
    int c = 0;
#pragma unroll
    for (int k = 0; k < 8; k++) { lc_out[k] = cnt[NB - 1 - (base + k)]; c += lc_out[k]; }
    int inc = c;
#pragma unroll
    for (int o = 1; o < 32; o <<= 1) {
        int n = __shfl_up_sync(0xFFFFFFFFu, inc, o);
        if (lane >= o) inc += n;
    }
    if (lane == 31) s_w[w] = inc;
    __syncthreads();
    if (tid == 0) {
        int rc = 0;
        for (int i = 0; i < 8; i++) { int v = s_w[i]; s_w[i] = rc; rc += v; }
    }
    __syncthreads();
    int epc = s_w[w] + inc - c;
    if (epc < R && R <= epc + c) {
        int rc = epc;
#pragma unroll
        for (int k = 0; k < 8; k++) {
            int idx = NB - 1 - (base + k);
            if (rc + lc_out[k] >= R) { *s_idx = (unsigned)idx; *s_rem = R - rc; break; }
            rc += lc_out[k];
        }
    }
    __syncthreads();
}

// ---------------- k_mh: max prior half extents (idempotent across replays) ----------------
__global__ void __launch_bounds__(256) k_mh(const float4* __restrict__ priors) {
    int g = blockIdx.x * 256 + threadIdx.x;
    int lane = threadIdx.x & 31;
    float hx = 0.0f, hy = 0.0f;
    for (int p = g; p < PP; p += 64 * 256) {
        float4 pr = priors[p];
        hx = fmaxf(hx, pr.z);
        hy = fmaxf(hy, pr.w);
    }
    hx = __fmul_rn(0.5f, hx);   // exact (×0.5)
    hy = __fmul_rn(0.5f, hy);
#pragma unroll
    for (int o = 16; o > 0; o >>= 1) {
        hx = fmaxf(hx, __shfl_down_sync(0xFFFFFFFFu, hx, o));
        hy = fmaxf(hy, __shfl_down_sync(0xFFFFFFFFu, hy, o));
    }
    if (lane == 0) {
        atomicMax(&g_mhx, __float_as_int(hx));
        atomicMax(&g_mhy, __float_as_int(hy));
    }
}

// ---------------- K0: zero accumulators ----------------
__global__ void __launch_bounds__(256) k_zero() {
    int g = blockIdx.x * 256 + threadIdx.x;
    for (int i = g; i < BB * NB; i += 16384) {
        ((int*)g_h1c)[i] = 0;
        ((int*)g_h2c)[i] = 0;
        ((int*)g_h3c)[i] = 0;
    }
    if (g < BB) { g_poscnt[g] = 0; g_posloss[g] = 0.0; g_sgt[g] = 0.0; }
    if (g == BB) { g_lossl = 0.0; g_ctr = 0; }
}

// ---------------- kseed: seeds (warp-per-truth over SEEDN priors) + cell masks ----------------
__global__ void __launch_bounds__(256) kseed(const float4* __restrict__ priors,
                                             const float*  __restrict__ targets) {
    int b = blockIdx.x, half = blockIdx.y;
    int tid = threadIdx.x, w = tid >> 5, lane = tid & 31;
    __shared__ float4 str[TT];
    __shared__ float s_mhx, s_mhy;
    if (tid < TT) {
        const float* tb = targets + (b * TT + tid) * 5;
        str[tid] = make_float4(tb[0], tb[1], tb[2], tb[3]);
    }
    if (tid == 0) {
        s_mhx = __fadd_rn(__int_as_float(g_mhx), 1e-5f);
        s_mhy = __fadd_rn(__int_as_float(g_mhy), 1e-5f);
    }
    __syncthreads();

    // ---- conservative truth masks for 512 cells (this half) ----
    float mhx = s_mhx, mhy = s_mhy;
    for (int c = tid; c < 512; c += 256) {
        int cell = half * 512 + c;
        int ci = cell & 31, cj = cell >> 5;
        float clx = ci * 0.03125f, chx = __fadd_rn(clx, 0.03125f);
        float cly = cj * 0.03125f, chy = __fadd_rn(cly, 0.03125f);
        unsigned m = 0;
#pragma unroll
        for (int t = 0; t < TT; t++) {
            float4 a = str[t];
            bool in = (__fsub_rn(a.x, mhx) <= chx) && (clx <= __fadd_rn(a.z, mhx))
                   && (__fsub_rn(a.y, mhy) <= chy) && (cly <= __fadd_rn(a.w, mhy));
            if (in) m |= (1u << t);
        }
        g_tmask[b][cell] = (unsigned short)m;
    }

    // ---- seed: warp w handles truth t = half*8 + w ----
    int t = half * 8 + w;
    float4 a = str[t];
    float ca = __fmul_rn(__fsub_rn(a.z, a.x), __fsub_rn(a.w, a.y));
    float bi = -1.0f, bd = 1.0f; unsigned bp = 0;
#pragma unroll 4
    for (int i = 0; i < SEEDN; i += 32) {
        int p = i + lane;
        Box bx = mkbox(priors[p]);
        float inter, den;
        iou_id(bx, a, ca, inter, den);
        if (__fmul_rn(inter, bd) > __fmul_rn(bi, den)) { bi = inter; bd = den; bp = p; }
    }
#pragma unroll
    for (int o = 16; o > 0; o >>= 1) {
        float oi = __shfl_down_sync(0xFFFFFFFFu, bi, o);
        float od = __shfl_down_sync(0xFFFFFFFFu, bd, o);
        unsigned op_ = __shfl_down_sync(0xFFFFFFFFu, bp, o);
        if (__fmul_rn(oi, bd) > __fmul_rn(bi, od)) { bi = oi; bd = od; bp = op_; }
    }
    if (lane == 0) {
        float iou = __fdiv_rn(bi, bd);
        g_skey[b][t] = ((unsigned long long)__float_as_uint(iou) << 32)
                     | (unsigned long long)(0xFFFFFFFFu - bp);   // exclusive owner
    }
}

// ---------------- K1: mask-gated match + losses + level-1 histogram ----------------
__global__ void __launch_bounds__(BLK, 2) k1(const float4* __restrict__ loc,
                                             const float2* __restrict__ conf,
                                             const float4* __restrict__ priors,
                                             const float*  __restrict__ targets) {
    int b = blockIdx.y, tid = threadIdx.x, lane = tid & 31;
    __shared__ float4 tr[TT];
    __shared__ float  cA[TT];
    __shared__ unsigned short smask[1024];
    __shared__ int    sc[NB];
    for (int i = tid; i < NB; i += BLK) sc[i] = 0;
    for (int i = tid; i < 512; i += BLK)
        ((unsigned*)smask)[i] = ((const unsigned*)g_tmask[b])[i];
    if (tid < TT) {
        const float* tb = targets + (b * TT + tid) * 5;
        float4 v = make_float4(tb[0], tb[1], tb[2], tb[3]);
        tr[tid] = v;
        cA[tid] = __fmul_rn(__fsub_rn(v.z, v.x), __fsub_rn(v.w, v.y));
    }
    __syncthreads();

    float c_min = 1e30f;
#pragma unroll
    for (int t = 0; t < TT; t++)
        c_min = fminf(c_min, __uint_as_float((unsigned)(g_skey[b][t] >> 32)));

    float lossl = 0.0f, ploss = 0.0f;
    int pcnt = 0;
    int pbase = blockIdx.x * (BLK * IPT);
#pragma unroll 1
    for (int i = 0; i < IPT; i++) {
        int p = pbase + i * BLK + tid;
        float4 pr = priors[p];
        Box bx = mkbox(pr);

        int cx = (int)__fmul_rn(pr.x, 32.0f);
        cx = min(max(cx, 0), 31);
        int cy = (int)__fmul_rn(pr.y, 32.0f);
        cy = min(max(cy, 0), 31);
        unsigned mm = smask[(cy << 5) + cx];

        // masked argmax: excluded truths have inter == 0 exactly -> identical
        // final (bi,bd,bti) whenever max IoU > 0; pos/gate identical otherwise.
        float bi = -1.0f, bd = 1.0f; int bti = 0;
        while (__any_sync(0xFFFFFFFFu, mm != 0u)) {
            bool act = (mm != 0u);
            int t = act ? (__ffs(mm) - 1) : 0;
            mm &= (mm - 1u);
            float inter, den;
            iou_id(bx, tr[t], cA[t], inter, den);
            if (act && (__fmul_rn(inter, bd) > __fmul_rn(bi, den))) {
                bi = inter; bd = den; bti = t;
            }
        }

        // cheap gate: can this prior beat ANY truth's current best?
        bool maybe = (__fmul_rn(bi, GMARGIN) >= __fmul_rn(c_min, bd));
        if (__any_sync(0xFFFFFFFFu, maybe)) {
#pragma unroll 1
            for (int t = 0; t < TT; t++) {
                float inter, den;
                iou_id(bx, tr[t], cA[t], inter, den);
                float ct = __uint_as_float((unsigned)(g_skey[b][t] >> 32));
                bool cand = maybe &&
                    (__fmul_rn(inter, GMARGIN) >= __fmul_rn(ct, den));
                if (__ballot_sync(0xFFFFFFFFu, cand)) {
                    float ci = cand ? inter : -1.0f;
                    float cd = cand ? den : 1.0f;
                    unsigned cp = (unsigned)p;
#pragma unroll
                    for (int o = 16; o > 0; o >>= 1) {
                        float oi = __shfl_down_sync(0xFFFFFFFFu, ci, o);
                        float od = __shfl_down_sync(0xFFFFFFFFu, cd, o);
                        unsigned op_ = __shfl_down_sync(0xFFFFFFFFu, cp, o);
                        if (__fmul_rn(oi, cd) > __fmul_rn(ci, od)) { ci = oi; cd = od; cp = op_; }
                    }
                    if (lane == 0 && ci >= 0.0f) {
                        float iou = __fdiv_rn(ci, cd);
                        unsigned long long key =
                            ((unsigned long long)__float_as_uint(iou) << 32) |
                            (unsigned long long)(0xFFFFFFFFu - cp);
                        atomicMax(&g_skey[b][t], key);
                    }
                }
            }
        }

        bool pos = (__fmul_rn(2.0f, bi) >= bd);
        float2 c = conf[(size_t)b * PP + p];
        float lse = lse2(c);
        float mv = pos ? 0.0f : __fsub_rn(lse, c.x);
        unsigned bits = __float_as_uint(mv);
        g_mine[b][p] = bits;
        unsigned bin = bits >> 21;
        unsigned peers = __match_any_sync(0xFFFFFFFFu, bin);
        if (lane == __ffs(peers) - 1) atomicAdd(&sc[bin], __popc(peers));
        if (pos) {
            pcnt++;
            ploss += __fsub_rn(lse, c.y);
            lossl += loc_sl1(loc[(size_t)b * PP + p], tr[bti], pr);
        }
    }

#pragma unroll
    for (int o = 16; o > 0; o >>= 1) {
        lossl += __shfl_down_sync(0xFFFFFFFFu, lossl, o);
        ploss += __shfl_down_sync(0xFFFFFFFFu, ploss, o);
        pcnt  += __shfl_down_sync(0xFFFFFFFFu, pcnt, o);
    }
    if (lane == 0) {
        if (lossl != 0.0f) atomicAdd(&g_lossl, (double)lossl);
        if (pcnt) {
            atomicAdd(&g_poscnt[b], pcnt);
            atomicAdd(&g_posloss[b], (double)ploss);
        }
    }
    __syncthreads();
    for (int i = tid; i < NB; i += BLK) {
        int cv = sc[i];
        if (cv) atomicAdd(&g_h1c[b][i], cv);
    }
}

// ---------------- K2: best-prior override fixup — thread per (b,t) ----------------
__global__ void __launch_bounds__(512) k_fix(const float4* __restrict__ loc,
                                             const float2* __restrict__ conf,
                                             const float4* __restrict__ priors,
                                             const float*  __restrict__ targets) {
    int tid = threadIdx.x;
    int b = tid >> 4, t = tid & 15;
    __shared__ float4   str[BB][TT];
    __shared__ float    scA[BB][TT];
    __shared__ unsigned sps[BB][TT];
    {
        const float* tb = targets + (b * TT + t) * 5;
        float4 v = make_float4(tb[0], tb[1], tb[2], tb[3]);
        str[b][t] = v;
        scA[b][t] = __fmul_rn(__fsub_rn(v.z, v.x), __fsub_rn(v.w, v.y));
        sps[b][t] = 0xFFFFFFFFu - (unsigned)(g_skey[b][t] & 0xFFFFFFFFull);
    }
    __syncthreads();

    unsigned p = sps[b][t];
    bool last = true;
#pragma unroll
    for (int t2 = 0; t2 < TT; t2++)
        if (t2 > t && sps[b][t2] == p) last = false;
    if (!last) return;                       // last write wins

    float4 pr = priors[p];
    Box bx = mkbox(pr);
    float bi, bd; int bti;
    match_idx(bx, str[b], scA[b], bi, bd, bti);
    bool pos_old = (__fmul_rn(2.0f, bi) >= bd);
    float2 c = conf[(size_t)b * PP + p];
    float lse = lse2(c);
    float4 ld = loc[(size_t)b * PP + p];
    float sl_new = loc_sl1(ld, str[b][t], pr);
    double dl = 0.0;
    if (pos_old) {
        if (bti != t) dl = (double)sl_new - (double)loc_sl1(ld, str[b][bti], pr);
    } else {
        dl = (double)sl_new;
        atomicAdd(&g_poscnt[b], 1);
        atomicAdd(&g_posloss[b], (double)__fsub_rn(lse, c.y));
        float mo = __fsub_rn(lse, c.x);      // bit-identical to k1's mv
        unsigned ob = __float_as_uint(mo) >> 21;
        atomicSub(&g_h1c[b][ob], 1);
        atomicAdd(&g_h1c[b][0], 1);
        g_mine[b][p] = 0u;
    }
    if (dl != 0.0) atomicAdd(&g_lossl, dl);
}

// ---------------- k_fa: in-block level-0 select + level-1 histogram ----------------
__global__ void __launch_bounds__(256) k_fa() {
    int b = blockIdx.y, tid = threadIdx.x;
    __shared__ int sc[NB];
    __shared__ int s_w[8];
    __shared__ unsigned s_idx;
    __shared__ int s_rem;
    for (int i = tid; i < NB; i += 256) sc[i] = 0;

    int k3 = 3 * g_poscnt[b];
    int R = (k3 < PP - 1) ? k3 : (PP - 1);
    int lc[8];
    scan_desc(g_h1c[b], R, tid, s_w, &s_idx, &s_rem, lc);
    unsigned pref = s_idx;

    const uint4* mp = (const uint4*)&g_mine[b][0];
    int base = blockIdx.x * (PP / 4 / NBLKF);
#pragma unroll 2
    for (int i = tid; i < PP / 4 / NBLKF; i += 256) {
        uint4 v = mp[base + i];
        if ((v.x >> 21) == pref) atomicAdd(&sc[(v.x >> 10) & 0x7FFu], 1);
        if ((v.y >> 21) == pref) atomicAdd(&sc[(v.y >> 10) & 0x7FFu], 1);
        if ((v.z >> 21) == pref) atomicAdd(&sc[(v.z >> 10) & 0x7FFu], 1);
        if ((v.w >> 21) == pref) atomicAdd(&sc[(v.w >> 10) & 0x7FFu], 1);
    }
    __syncthreads();
    for (int i = tid; i < NB; i += 256)
        if (sc[i]) atomicAdd(&g_h2c[b][i], sc[i]);
    if (tid == 0 && blockIdx.x == 0) { g_pref0[b] = pref; g_R1[b] = s_rem; }
}

// ---------------- k_fb: in-block level-1 select + level-2 hist + upper sum ----------------
__global__ void __launch_bounds__(256) k_fb() {
    int b = blockIdx.y, tid = threadIdx.x, lane = tid & 31;
    __shared__ int sc[NB];
    __shared__ int s_w[8];
    __shared__ unsigned s_idx;
    __shared__ int s_rem;
    for (int i = tid; i < NB; i += 256) sc[i] = 0;

    int lc[8];
    scan_desc(g_h2c[b], g_R1[b], tid, s_w, &s_idx, &s_rem, lc);
    unsigned pref22 = (g_pref0[b] << 11) | s_idx;

    double fsum = 0.0;
    const uint4* mp = (const uint4*)&g_mine[b][0];
    int base = blockIdx.x * (PP / 4 / NBLKF);
#pragma unroll 2
    for (int i = tid; i < PP / 4 / NBLKF; i += 256) {
        uint4 v = mp[base + i];
        unsigned t0 = v.x >> 10, t1 = v.y >> 10, t2 = v.z >> 10, t3 = v.w >> 10;
        if (t0 == pref22) atomicAdd(&sc[v.x & 0x3FFu], 1);
        else if (t0 > pref22) fsum += (double)__uint_as_float(v.x);
        if (t1 == pref22) atomicAdd(&sc[v.y & 0x3FFu], 1);
        else if (t1 > pref22) fsum += (double)__uint_as_float(v.y);
        if (t2 == pref22) atomicAdd(&sc[v.z & 0x3FFu], 1);
        else if (t2 > pref22) fsum += (double)__uint_as_float(v.z);
        if (t3 == pref22) atomicAdd(&sc[v.w & 0x3FFu], 1);
        else if (t3 > pref22) fsum += (double)__uint_as_float(v.w);
    }
    __syncthreads();
    for (int i = tid; i < NB; i += 256)
        if (sc[i]) atomicAdd(&g_h3c[b][i], sc[i]);
#pragma unroll
    for (int o = 16; o > 0; o >>= 1)
        fsum += __shfl_down_sync(0xFFFFFFFFu, fsum, o);
    if (lane == 0 && fsum != 0.0) atomicAdd(&g_sgt[b], fsum);
    if (tid == 0 && blockIdx.x == 0) { g_pref22[b] = pref22; g_R2[b] = s_rem; }
}

// ---------------- k_last: level-2 select + exact top-K sum + final combine ----------------
__global__ void __launch_bounds__(256) k_last(float* __restrict__ out) {
    int b = blockIdx.x, tid = threadIdx.x;
    __shared__ int s_w[8];
    __shared__ unsigned s_idx;
    __shared__ int s_rem;
    __shared__ double s_ws[8];
    __shared__ int s_last;

    int lc[8];
    scan_desc(g_h3c[b], g_R2[b], tid, s_w, &s_idx, &s_rem, lc);
    unsigned pref = g_pref22[b];
    unsigned idx3 = s_idx;
    int R3 = s_rem;

    double s = 0.0;
    int base = tid * 8;
#pragma unroll
    for (int k = 0; k < 8; k++) {
        unsigned idx = (unsigned)(NB - 1 - (base + k));
        if (idx > idx3 && lc[k])
            s += (double)lc[k] * (double)__uint_as_float((pref << 10) | idx);
    }
#pragma unroll
    for (int o = 16; o > 0; o >>= 1)
        s += __shfl_down_sync(0xFFFFFFFFu, s, o);
    if ((tid & 31) == 0) s_ws[tid >> 5] = s;
    __syncthreads();
    if (tid == 0) {
        double tot = 0.0;
        for (int w = 0; w < 8; w++) tot += s_ws[w];
        g_topsum[b] = g_sgt[b] + tot +
                      (double)R3 * (double)__uint_as_float((pref << 10) | idx3);
        __threadfence();
        int done = atomicAdd(&g_ctr, 1);
        s_last = (done == BB - 1) ? 1 : 0;
    }
    __syncthreads();
    if (s_last) {
        __threadfence();
        if (tid < 32) {
            int np = g_poscnt[tid];
            double lc2 = g_posloss[tid] + g_topsum[tid];
#pragma unroll
            for (int o = 16; o > 0; o >>= 1) {
                np  += __shfl_down_sync(0xFFFFFFFFu, np, o);
                lc2 += __shfl_down_sync(0xFFFFFFFFu, lc2, o);
            }
            if (tid == 0) {
                double N = (double)np;
                out[0] = (float)(g_lossl / N);
                out[1] = (float)(lc2 / N);
            }
        }
    }
}

// ---------------- launch ----------------
extern "C" void kernel_launch(void* const* d_in, const int* in_sizes, int n_in,
                              void* d_out, int out_size) {
    const float4* loc     = (const float4*)d_in[0];
    const float2* conf    = (const float2*)d_in[1];
    const float4* priors  = (const float4*)d_in[2];
    const float*  targets = (const float*)d_in[3];
    float* out = (float*)d_out;

    k_mh<<<64, 256>>>(priors);                          // 1
    k_zero<<<64, 256>>>();                              // 2
    dim3 gs(BB, 2);
    kseed<<<gs, 256>>>(priors, targets);                // 3
    dim3 g1(NBLK, BB);
    k1<<<g1, BLK>>>(loc, conf, priors, targets);        // 4 -> ncu captures this
    k_fix<<<1, 512>>>(loc, conf, priors, targets);      // 5
    dim3 gf(NBLKF, BB);
    k_fa<<<gf, 256>>>();                                // 6
    k_fb<<<gf, 256>>>();                                // 7
    k_last<<<BB, 256>>>(out);                           // 8
}

// round 15
// speedup vs baseline: 1.8380x; 1.0154x over previous
#include <cuda_runtime.h>

#define BB 32
#define PP 65536
#define TT 16
#define NB 2048
#define BLK 256
#define IPT 16
#define NBLK (PP/(BLK*IPT))   // 16 blocks per batch in k1
#define NBLKF 32              // 32 blocks per batch in filters
#define SEEDN 8192
#define GMARGIN 1.000002f

// ---------------- device scratch ----------------
__device__ unsigned int       g_mine[BB][PP];
__device__ unsigned long long g_skey[BB][TT];
__device__ unsigned short     g_tmask[BB][1024];
__device__ int    g_mhx;      // float bits of max prior half-width (persistent, idempotent)
__device__ int    g_mhy;
__device__ int    g_h1c[BB][NB];
__device__ int    g_h2c[BB][NB];
__device__ int    g_h3c[BB][NB];
__device__ int    g_poscnt[BB];
__device__ double g_posloss[BB];
__device__ double g_lossl;
__device__ unsigned g_pref0[BB];
__device__ int    g_R1[BB];
__device__ unsigned g_pref22[BB];
__device__ int    g_R2[BB];
__device__ double g_sgt[BB];
__device__ double g_topsum[BB];
__device__ int    g_ctr;

// ---------------- helpers (bit-identical across kernels) ----------------
struct Box { float x0, y0, x1, y1, areaB; };

__device__ __forceinline__ Box mkbox(float4 pr) {
    Box b;
    float hx = __fmul_rn(0.5f, pr.z), hy = __fmul_rn(0.5f, pr.w);
    b.x0 = __fsub_rn(pr.x, hx); b.y0 = __fsub_rn(pr.y, hy);
    b.x1 = __fadd_rn(pr.x, hx); b.y1 = __fadd_rn(pr.y, hy);
    b.areaB = __fmul_rn(__fsub_rn(b.x1, b.x0), __fsub_rn(b.y1, b.y0));
    return b;
}

__device__ __forceinline__ void iou_id(const Box& bx, float4 a, float ca,
                                       float& inter, float& den) {
    float w = fmaxf(__fsub_rn(fminf(a.z, bx.x1), fmaxf(a.x, bx.x0)), 0.0f);
    float h = fmaxf(__fsub_rn(fminf(a.w, bx.y1), fmaxf(a.y, bx.y0)), 0.0f);
    inter = __fmul_rn(w, h);
    den = __fsub_rn(__fadd_rn(ca, bx.areaB), inter);
}

// Full serial chain argmax (used off the hot path: k_fix).
__device__ __forceinline__ void match_idx(
    const Box& bx, const float4* tr, const float* cA,
    float& bi, float& bd, int& bti)
{
    bi = -1.0f; bd = 1.0f; bti = 0;
#pragma unroll
    for (int t = 0; t < TT; t++) {
        float inter, den;
        iou_id(bx, tr[t], cA[t], inter, den);
        if (__fmul_rn(inter, bd) > __fmul_rn(bi, den)) { bi = inter; bd = den; bti = t; }
    }
}

__device__ __forceinline__ float lse2(float2 c) {
    return __fadd_rn(fmaxf(c.x, c.y),
                     __logf(__fadd_rn(1.0f, __expf(-fabsf(__fsub_rn(c.x, c.y))))));
}

__device__ __forceinline__ float loc_sl1(float4 ld, float4 a, float4 pr) {
    float gx = ((a.x + a.z) * 0.5f - pr.x) / (0.1f * pr.z);
    float gy = ((a.y + a.w) * 0.5f - pr.y) / (0.1f * pr.w);
    float gw = __logf((a.z - a.x) / pr.z) / 0.2f;
    float gh = __logf((a.w - a.y) / pr.w) / 0.2f;
    float d0 = fabsf(ld.x - gx), d1 = fabsf(ld.y - gy);
    float d2 = fabsf(ld.z - gw), d3 = fabsf(ld.w - gh);
    return (d0 < 1.f ? 0.5f * d0 * d0 : d0 - 0.5f)
         + (d1 < 1.f ? 0.5f * d1 * d1 : d1 - 0.5f)
         + (d2 < 1.f ? 0.5f * d2 * d2 : d2 - 0.5f)
         + (d3 < 1.f ? 0.5f * d3 * d3 : d3 - 0.5f);
}

// Parallel descending radix-select over NB bins; cnt may be global or shared.
__device__ __forceinline__ void scan_desc(const int* cnt, int R, int tid,
                                          int* s_w, unsigned* s_idx, int* s_rem,
                                          int* lc_out)
{
    int lane = tid & 31, w = tid >> 5;
    int base = tid * 8;
    int c = 0;
#pragma unroll
    for (int k = 0; k < 8; k++) { lc_out[k] = cnt[NB - 1 - (base + k)]; c += lc_out[k]; }
    int inc = c;
#pragma unroll
    for (int o = 1; o < 32; o <<= 1) {
        int n = __shfl_up_sync(0xFFFFFFFFu, inc, o);
        if (lane >= o) inc += n;
    }
    if (lane == 31) s_w[w] = inc;
    __syncthreads();
    if (tid == 0) {
        int rc = 0;
        for (int i = 0; i < 8; i++) { int v = s_w[i]; s_w[i] = rc; rc += v; }
    }
    __syncthreads();
    int epc = s_w[w] + inc - c;
    if (epc < R && R <= epc + c) {
        int rc = epc;
#pragma unroll
        for (int k = 0; k < 8; k++) {
            int idx = NB - 1 - (base + k);
            if (rc + lc_out[k] >= R) { *s_idx = (unsigned)idx; *s_rem = R - rc; break; }
            rc += lc_out[k];
        }
    }
    __syncthreads();
}

// ---------------- k_mh: max prior half extents (idempotent across replays) ----------------
__global__ void __launch_bounds__(256) k_mh(const float4* __restrict__ priors) {
    int g = blockIdx.x * 256 + threadIdx.x;
    int lane = threadIdx.x & 31;
    float hx = 0.0f, hy = 0.0f;
    for (int p = g; p < PP; p += 64 * 256) {
        float4 pr = priors[p];
        hx = fmaxf(hx, pr.z);
        hy = fmaxf(hy, pr.w);
    }
    hx = __fmul_rn(0.5f, hx);   // exact (×0.5)
    hy = __fmul_rn(0.5f, hy);
#pragma unroll
    for (int o = 16; o > 0; o >>= 1) {
        hx = fmaxf(hx, __shfl_down_sync(0xFFFFFFFFu, hx, o));
        hy = fmaxf(hy, __shfl_down_sync(0xFFFFFFFFu, hy, o));
    }
    if (lane == 0) {
        atomicMax(&g_mhx, __float_as_int(hx));
        atomicMax(&g_mhy, __float_as_int(hy));
    }
}

// ---------------- K0: zero accumulators ----------------
__global__ void __launch_bounds__(256) k_zero() {
    int g = blockIdx.x * 256 + threadIdx.x;
    for (int i = g; i < BB * NB; i += 16384) {
        ((int*)g_h1c)[i] = 0;
        ((int*)g_h2c)[i] = 0;
        ((int*)g_h3c)[i] = 0;
    }
    if (g < BB) { g_poscnt[g] = 0; g_posloss[g] = 0.0; g_sgt[g] = 0.0; }
    if (g == BB) { g_lossl = 0.0; g_ctr = 0; }
}

// ---------------- kseed: seeds (warp-per-truth over SEEDN priors) + cell masks ----------------
__global__ void __launch_bounds__(256) kseed(const float4* __restrict__ priors,
                                             const float*  __restrict__ targets) {
    int b = blockIdx.x, half = blockIdx.y;
    int tid = threadIdx.x, w = tid >> 5, lane = tid & 31;
    __shared__ float4 str[TT];
    __shared__ float s_mhx, s_mhy;
    if (tid < TT) {
        const float* tb = targets + (b * TT + tid) * 5;
        str[tid] = make_float4(tb[0], tb[1], tb[2], tb[3]);
    }
    if (tid == 0) {
        s_mhx = __fadd_rn(__int_as_float(g_mhx), 1e-5f);
        s_mhy = __fadd_rn(__int_as_float(g_mhy), 1e-5f);
    }
    __syncthreads();

    // ---- conservative truth masks for 512 cells (this half) ----
    float mhx = s_mhx, mhy = s_mhy;
    for (int c = tid; c < 512; c += 256) {
        int cell = half * 512 + c;
        int ci = cell & 31, cj = cell >> 5;
        float clx = ci * 0.03125f, chx = __fadd_rn(clx, 0.03125f);
        float cly = cj * 0.03125f, chy = __fadd_rn(cly, 0.03125f);
        unsigned m = 0;
#pragma unroll
        for (int t = 0; t < TT; t++) {
            float4 a = str[t];
            bool in = (__fsub_rn(a.x, mhx) <= chx) && (clx <= __fadd_rn(a.z, mhx))
                   && (__fsub_rn(a.y, mhy) <= chy) && (cly <= __fadd_rn(a.w, mhy));
            if (in) m |= (1u << t);
        }
        g_tmask[b][cell] = (unsigned short)m;
    }

    // ---- seed: warp w handles truth t = half*8 + w ----
    int t = half * 8 + w;
    float4 a = str[t];
    float ca = __fmul_rn(__fsub_rn(a.z, a.x), __fsub_rn(a.w, a.y));
    float bi = -1.0f, bd = 1.0f; unsigned bp = 0;
#pragma unroll 4
    for (int i = 0; i < SEEDN; i += 32) {
        int p = i + lane;
        Box bx = mkbox(priors[p]);
        float inter, den;
        iou_id(bx, a, ca, inter, den);
        if (__fmul_rn(inter, bd) > __fmul_rn(bi, den)) { bi = inter; bd = den; bp = p; }
    }
#pragma unroll
    for (int o = 16; o > 0; o >>= 1) {
        float oi = __shfl_down_sync(0xFFFFFFFFu, bi, o);
        float od = __shfl_down_sync(0xFFFFFFFFu, bd, o);
        unsigned op_ = __shfl_down_sync(0xFFFFFFFFu, bp, o);
        if (__fmul_rn(oi, bd) > __fmul_rn(bi, od)) { bi = oi; bd = od; bp = op_; }
    }
    if (lane == 0) {
        float iou = __fdiv_rn(bi, bd);
        g_skey[b][t] = ((unsigned long long)__float_as_uint(iou) << 32)
                     | (unsigned long long)(0xFFFFFFFFu - bp);   // exclusive owner
    }
}

// ---------------- K1: mask-gated match + losses + level-1 histogram ----------------
__global__ void __launch_bounds__(BLK, 4) k1(const float4* __restrict__ loc,
                                             const float2* __restrict__ conf,
                                             const float4* __restrict__ priors,
                                             const float*  __restrict__ targets) {
    int b = blockIdx.y, tid = threadIdx.x, lane = tid & 31;
    __shared__ float4 tr[TT];
    __shared__ float  cA[TT];
    __shared__ unsigned short smask[1024];
    __shared__ int    sc[NB];
    for (int i = tid; i < NB; i += BLK) sc[i] = 0;
    for (int i = tid; i < 512; i += BLK)
        ((unsigned*)smask)[i] = ((const unsigned*)g_tmask[b])[i];
    if (tid < TT) {
        const float* tb = targets + (b * TT + tid) * 5;
        float4 v = make_float4(tb[0], tb[1], tb[2], tb[3]);
        tr[tid] = v;
        cA[tid] = __fmul_rn(__fsub_rn(v.z, v.x), __fsub_rn(v.w, v.y));
    }
    __syncthreads();

    float c_min = 1e30f;
#pragma unroll
    for (int t = 0; t < TT; t++)
        c_min = fminf(c_min, __uint_as_float((unsigned)(g_skey[b][t] >> 32)));

    float lossl = 0.0f, ploss = 0.0f;
    int pcnt = 0;
    int pbase = blockIdx.x * (BLK * IPT);
#pragma unroll 1
    for (int i = 0; i < IPT; i++) {
        int p = pbase + i * BLK + tid;
        float4 pr = priors[p];
        Box bx = mkbox(pr);

        int cx = (int)__fmul_rn(pr.x, 32.0f);
        cx = min(max(cx, 0), 31);
        int cy = (int)__fmul_rn(pr.y, 32.0f);
        cy = min(max(cy, 0), 31);
        unsigned mm = smask[(cy << 5) + cx];

        // masked argmax, plain divergent loop: excluded truths have inter == 0
        // exactly -> identical final (bi,bd,bti) whenever max IoU > 0;
        // pos/gate identical otherwise.
        float bi = -1.0f, bd = 1.0f; int bti = 0;
        while (mm) {
            int t = __ffs(mm) - 1;
            mm &= (mm - 1u);
            float inter, den;
            iou_id(bx, tr[t], cA[t], inter, den);
            if (__fmul_rn(inter, bd) > __fmul_rn(bi, den)) {
                bi = inter; bd = den; bti = t;
            }
        }

        // cheap gate: can this prior beat ANY truth's current best?
        bool maybe = (__fmul_rn(bi, GMARGIN) >= __fmul_rn(c_min, bd));
        if (__any_sync(0xFFFFFFFFu, maybe)) {
#pragma unroll 1
            for (int t = 0; t < TT; t++) {
                float inter, den;
                iou_id(bx, tr[t], cA[t], inter, den);
                float ct = __uint_as_float((unsigned)(g_skey[b][t] >> 32));
                bool cand = maybe &&
                    (__fmul_rn(inter, GMARGIN) >= __fmul_rn(ct, den));
                if (__ballot_sync(0xFFFFFFFFu, cand)) {
                    float ci = cand ? inter : -1.0f;
                    float cd = cand ? den : 1.0f;
                    unsigned cp = (unsigned)p;
#pragma unroll
                    for (int o = 16; o > 0; o >>= 1) {
                        float oi = __shfl_down_sync(0xFFFFFFFFu, ci, o);
                        float od = __shfl_down_sync(0xFFFFFFFFu, cd, o);
                        unsigned op_ = __shfl_down_sync(0xFFFFFFFFu, cp, o);
                        if (__fmul_rn(oi, cd) > __fmul_rn(ci, od)) { ci = oi; cd = od; cp = op_; }
                    }
                    if (lane == 0 && ci >= 0.0f) {
                        float iou = __fdiv_rn(ci, cd);
                        unsigned long long key =
                            ((unsigned long long)__float_as_uint(iou) << 32) |
                            (unsigned long long)(0xFFFFFFFFu - cp);
                        atomicMax(&g_skey[b][t], key);
                    }
                }
            }
        }

        bool pos = (__fmul_rn(2.0f, bi) >= bd);
        float2 c = conf[(size_t)b * PP + p];
        float lse = lse2(c);
        float mv = pos ? 0.0f : __fsub_rn(lse, c.x);
        unsigned bits = __float_as_uint(mv);
        g_mine[b][p] = bits;
        unsigned bin = bits >> 21;
        unsigned peers = __match_any_sync(0xFFFFFFFFu, bin);
        if (lane == __ffs(peers) - 1) atomicAdd(&sc[bin], __popc(peers));
        if (pos) {
            pcnt++;
            ploss += __fsub_rn(lse, c.y);
            lossl += loc_sl1(loc[(size_t)b * PP + p], tr[bti], pr);
        }
    }

#pragma unroll
    for (int o = 16; o > 0; o >>= 1) {
        lossl += __shfl_down_sync(0xFFFFFFFFu, lossl, o);
        ploss += __shfl_down_sync(0xFFFFFFFFu, ploss, o);
        pcnt  += __shfl_down_sync(0xFFFFFFFFu, pcnt, o);
    }
    if (lane == 0) {
        if (lossl != 0.0f) atomicAdd(&g_lossl, (double)lossl);
        if (pcnt) {
            atomicAdd(&g_poscnt[b], pcnt);
            atomicAdd(&g_posloss[b], (double)ploss);
        }
    }
    __syncthreads();
    for (int i = tid; i < NB; i += BLK) {
        int cv = sc[i];
        if (cv) atomicAdd(&g_h1c[b][i], cv);
    }
}

// ---------------- K2: best-prior override fixup — thread per (b,t) ----------------
__global__ void __launch_bounds__(512) k_fix(const float4* __restrict__ loc,
                                             const float2* __restrict__ conf,
                                             const float4* __restrict__ priors,
                                             const float*  __restrict__ targets) {
    int tid = threadIdx.x;
    int b = tid >> 4, t = tid & 15;
    __shared__ float4   str[BB][TT];
    __shared__ float    scA[BB][TT];
    __shared__ unsigned sps[BB][TT];
    {
        const float* tb = targets + (b * TT + t) * 5;
        float4 v = make_float4(tb[0], tb[1], tb[2], tb[3]);
        str[b][t] = v;
        scA[b][t] = __fmul_rn(__fsub_rn(v.z, v.x), __fsub_rn(v.w, v.y));
        sps[b][t] = 0xFFFFFFFFu - (unsigned)(g_skey[b][t] & 0xFFFFFFFFull);
    }
    __syncthreads();

    unsigned p = sps[b][t];
    bool last = true;
#pragma unroll
    for (int t2 = 0; t2 < TT; t2++)
        if (t2 > t && sps[b][t2] == p) last = false;
    if (!last) return;                       // last write wins

    float4 pr = priors[p];
    Box bx = mkbox(pr);
    float bi, bd; int bti;
    match_idx(bx, str[b], scA[b], bi, bd, bti);
    bool pos_old = (__fmul_rn(2.0f, bi) >= bd);
    float2 c = conf[(size_t)b * PP + p];
    float lse = lse2(c);
    float4 ld = loc[(size_t)b * PP + p];
    float sl_new = loc_sl1(ld, str[b][t], pr);
    double dl = 0.0;
    if (pos_old) {
        if (bti != t) dl = (double)sl_new - (double)loc_sl1(ld, str[b][bti], pr);
    } else {
        dl = (double)sl_new;
        atomicAdd(&g_poscnt[b], 1);
        atomicAdd(&g_posloss[b], (double)__fsub_rn(lse, c.y));
        float mo = __fsub_rn(lse, c.x);      // bit-identical to k1's mv
        unsigned ob = __float_as_uint(mo) >> 21;
        atomicSub(&g_h1c[b][ob], 1);
        atomicAdd(&g_h1c[b][0], 1);
        g_mine[b][p] = 0u;
    }
    if (dl != 0.0) atomicAdd(&g_lossl, dl);
}

// ---------------- k_fa: in-block level-0 select + level-1 histogram ----------------
__global__ void __launch_bounds__(256) k_fa() {
    int b = blockIdx.y, tid = threadIdx.x;
    __shared__ int sc[NB];
    __shared__ int s_w[8];
    __shared__ unsigned s_idx;
    __shared__ int s_rem;
    for (int i = tid; i < NB; i += 256) sc[i] = 0;

    int k3 = 3 * g_poscnt[b];
    int R = (k3 < PP - 1) ? k3 : (PP - 1);
    int lc[8];
    scan_desc(g_h1c[b], R, tid, s_w, &s_idx, &s_rem, lc);
    unsigned pref = s_idx;

    const uint4* mp = (const uint4*)&g_mine[b][0];
    int base = blockIdx.x * (PP / 4 / NBLKF);
#pragma unroll 2
    for (int i = tid; i < PP / 4 / NBLKF; i += 256) {
        uint4 v = mp[base + i];
        if ((v.x >> 21) == pref) atomicAdd(&sc[(v.x >> 10) & 0x7FFu], 1);
        if ((v.y >> 21) == pref) atomicAdd(&sc[(v.y >> 10) & 0x7FFu], 1);
        if ((v.z >> 21) == pref) atomicAdd(&sc[(v.z >> 10) & 0x7FFu], 1);
        if ((v.w >> 21) == pref) atomicAdd(&sc[(v.w >> 10) & 0x7FFu], 1);
    }
    __syncthreads();
    for (int i = tid; i < NB; i += 256)
        if (sc[i]) atomicAdd(&g_h2c[b][i], sc[i]);
    if (tid == 0 && blockIdx.x == 0) { g_pref0[b] = pref; g_R1[b] = s_rem; }
}

// ---------------- k_fb: in-block level-1 select + level-2 hist + upper sum ----------------
__global__ void __launch_bounds__(256) k_fb() {
    int b = blockIdx.y, tid = threadIdx.x, lane = tid & 31;
    __shared__ int sc[NB];
    __shared__ int s_w[8];
    __shared__ unsigned s_idx;
    __shared__ int s_rem;
    for (int i = tid; i < NB; i += 256) sc[i] = 0;

    int lc[8];
    scan_desc(g_h2c[b], g_R1[b], tid, s_w, &s_idx, &s_rem, lc);
    unsigned pref22 = (g_pref0[b] << 11) | s_idx;

    double fsum = 0.0;
    const uint4* mp = (const uint4*)&g_mine[b][0];
    int base = blockIdx.x * (PP / 4 / NBLKF);
#pragma unroll 2
    for (int i = tid; i < PP / 4 / NBLKF; i += 256) {
        uint4 v = mp[base + i];
        unsigned t0 = v.x >> 10, t1 = v.y >> 10, t2 = v.z >> 10, t3 = v.w >> 10;
        if (t0 == pref22) atomicAdd(&sc[v.x & 0x3FFu], 1);
        else if (t0 > pref22) fsum += (double)__uint_as_float(v.x);
        if (t1 == pref22) atomicAdd(&sc[v.y & 0x3FFu], 1);
        else if (t1 > pref22) fsum += (double)__uint_as_float(v.y);
        if (t2 == pref22) atomicAdd(&sc[v.z & 0x3FFu], 1);
        else if (t2 > pref22) fsum += (double)__uint_as_float(v.z);
        if (t3 == pref22) atomicAdd(&sc[v.w & 0x3FFu], 1);
        else if (t3 > pref22) fsum += (double)__uint_as_float(v.w);
    }
    __syncthreads();
    for (int i = tid; i < NB; i += 256)
        if (sc[i]) atomicAdd(&g_h3c[b][i], sc[i]);
#pragma unroll
    for (int o = 16; o > 0; o >>= 1)
        fsum += __shfl_down_sync(0xFFFFFFFFu, fsum, o);
    if (lane == 0 && fsum != 0.0) atomicAdd(&g_sgt[b], fsum);
    if (tid == 0 && blockIdx.x == 0) { g_pref22[b] = pref22; g_R2[b] = s_rem; }
}

// ---------------- k_last: level-2 select + exact top-K sum + final combine ----------------
__global__ void __launch_bounds__(256) k_last(float* __restrict__ out) {
    int b = blockIdx.x, tid = threadIdx.x;
    __shared__ int s_w[8];
    __shared__ unsigned s_idx;
    __shared__ int s_rem;
    __shared__ double s_ws[8];
    __shared__ int s_last;

    int lc[8];
    scan_desc(g_h3c[b], g_R2[b], tid, s_w, &s_idx, &s_rem, lc);
    unsigned pref = g_pref22[b];
    unsigned idx3 = s_idx;
    int R3 = s_rem;

    double s = 0.0;
    int base = tid * 8;
#pragma unroll
    for (int k = 0; k < 8; k++) {
        unsigned idx = (unsigned)(NB - 1 - (base + k));
        if (idx > idx3 && lc[k])
            s += (double)lc[k] * (double)__uint_as_float((pref << 10) | idx);
    }
#pragma unroll
    for (int o = 16; o > 0; o >>= 1)
        s += __shfl_down_sync(0xFFFFFFFFu, s, o);
    if ((tid & 31) == 0) s_ws[tid >> 5] = s;
    __syncthreads();
    if (tid == 0) {
        double tot = 0.0;
        for (int w = 0; w < 8; w++) tot += s_ws[w];
        g_topsum[b] = g_sgt[b] + tot +
                      (double)R3 * (double)__uint_as_float((pref << 10) | idx3);
        __threadfence();
        int done = atomicAdd(&g_ctr, 1);
        s_last = (done == BB - 1) ? 1 : 0;
    }
    __syncthreads();
    if (s_last) {
        __threadfence();
        if (tid < 32) {
            int np = g_poscnt[tid];
            double lc2 = g_posloss[tid] + g_topsum[tid];
#pragma unroll
            for (int o = 16; o > 0; o >>= 1) {
                np  += __shfl_down_sync(0xFFFFFFFFu, np, o);
                lc2 += __shfl_down_sync(0xFFFFFFFFu, lc2, o);
            }
            if (tid == 0) {
                double N = (double)np;
                out[0] = (float)(g_lossl / N);
                out[1] = (float)(lc2 / N);
            }
        }
    }
}

// ---------------- launch ----------------
extern "C" void kernel_launch(void* const* d_in, const int* in_sizes, int n_in,
                              void* d_out, int out_size) {
    const float4* loc     = (const float4*)d_in[0];
    const float2* conf    = (const float2*)d_in[1];
    const float4* priors  = (const float4*)d_in[2];
    const float*  targets = (const float*)d_in[3];
    float* out = (float*)d_out;

    k_mh<<<64, 256>>>(priors);                          // 1
    k_zero<<<64, 256>>>();                              // 2
    dim3 gs(BB, 2);
    kseed<<<gs, 256>>>(priors, targets);                // 3
    dim3 g1(NBLK, BB);
    k1<<<g1, BLK>>>(loc, conf, priors, targets);        // 4 -> ncu captures this
    k_fix<<<1, 512>>>(loc, conf, priors, targets);      // 5
    dim3 gf(NBLKF, BB);
    k_fa<<<gf, 256>>>();                                // 6
    k_fb<<<gf, 256>>>();                                // 7
    k_last<<<BB, 256>>>(out);                           // 8
}

// round 16
// speedup vs baseline: 2.0805x; 1.1319x over previous
#include <cuda_runtime.h>

#define BB 32
#define PP 65536
#define TT 16
#define NB 2048
#define BLK 256
#define IPT 16
#define NBLK (PP/(BLK*IPT))   // 16 blocks per batch in k1
#define NBLKF 32              // 32 blocks per batch in filters
#define SEEDN 8192
#define GMARGIN 1.000002f

// ---------------- device scratch ----------------
__device__ unsigned int       g_mine[BB][PP];
__device__ unsigned long long g_skey[BB][TT];
__device__ unsigned short     g_tmask[BB][1024];
__device__ int    g_mhx;      // float bits of max prior half-width (idempotent)
__device__ int    g_mhy;
__device__ int    g_chist[1024];
__device__ int    g_cfill[1024];
__device__ float4 g_sp[PP];   // cell-sorted priors
__device__ int    g_sidx[PP]; // original index of sorted prior
__device__ int    g_h1c[BB][NB];
__device__ int    g_h2c[BB][NB];
__device__ int    g_h3c[BB][NB];
__device__ int    g_poscnt[BB];
__device__ double g_posloss[BB];
__device__ double g_lossl;
__device__ unsigned g_pref0[BB];
__device__ int    g_R1[BB];
__device__ unsigned g_pref22[BB];
__device__ int    g_R2[BB];
__device__ double g_sgt[BB];
__device__ double g_topsum[BB];
__device__ int    g_ctr;

// ---------------- helpers (bit-identical across kernels) ----------------
struct Box { float x0, y0, x1, y1, areaB; };

__device__ __forceinline__ Box mkbox(float4 pr) {
    Box b;
    float hx = __fmul_rn(0.5f, pr.z), hy = __fmul_rn(0.5f, pr.w);
    b.x0 = __fsub_rn(pr.x, hx); b.y0 = __fsub_rn(pr.y, hy);
    b.x1 = __fadd_rn(pr.x, hx); b.y1 = __fadd_rn(pr.y, hy);
    b.areaB = __fmul_rn(__fsub_rn(b.x1, b.x0), __fsub_rn(b.y1, b.y0));
    return b;
}

__device__ __forceinline__ int cell_of(float4 pr) {
    int cx = (int)__fmul_rn(pr.x, 32.0f);
    cx = min(max(cx, 0), 31);
    int cy = (int)__fmul_rn(pr.y, 32.0f);
    cy = min(max(cy, 0), 31);
    return (cy << 5) + cx;
}

__device__ __forceinline__ void iou_id(const Box& bx, float4 a, float ca,
                                       float& inter, float& den) {
    float w = fmaxf(__fsub_rn(fminf(a.z, bx.x1), fmaxf(a.x, bx.x0)), 0.0f);
    float h = fmaxf(__fsub_rn(fminf(a.w, bx.y1), fmaxf(a.y, bx.y0)), 0.0f);
    inter = __fmul_rn(w, h);
    den = __fsub_rn(__fadd_rn(ca, bx.areaB), inter);
}

// Full serial chain argmax (used off the hot path: k_fix).
__device__ __forceinline__ void match_idx(
    const Box& bx, const float4* tr, const float* cA,
    float& bi, float& bd, int& bti)
{
    bi = -1.0f; bd = 1.0f; bti = 0;
#pragma unroll
    for (int t = 0; t < TT; t++) {
        float inter, den;
        iou_id(bx, tr[t], cA[t], inter, den);
        if (__fmul_rn(inter, bd) > __fmul_rn(bi, den)) { bi = inter; bd = den; bti = t; }
    }
}

__device__ __forceinline__ float lse2(float2 c) {
    return __fadd_rn(fmaxf(c.x, c.y),
                     __logf(__fadd_rn(1.0f, __expf(-fabsf(__fsub_rn(c.x, c.y))))));
}

__device__ __forceinline__ float loc_sl1(float4 ld, float4 a, float4 pr) {
    float gx = ((a.x + a.z) * 0.5f - pr.x) / (0.1f * pr.z);
    float gy = ((a.y + a.w) * 0.5f - pr.y) / (0.1f * pr.w);
    float gw = __logf((a.z - a.x) / pr.z) / 0.2f;
    float gh = __logf((a.w - a.y) / pr.w) / 0.2f;
    float d0 = fabsf(ld.x - gx), d1 = fabsf(ld.y - gy);
    float d2 = fabsf(ld.z - gw), d3 = fabsf(ld.w - gh);
    return (d0 < 1.f ? 0.5f * d0 * d0 : d0 - 0.5f)
         + (d1 < 1.f ? 0.5f * d1 * d1 : d1 - 0.5f)
         + (d2 < 1.f ? 0.5f * d2 * d2 : d2 - 0.5f)
         + (d3 < 1.f ? 0.5f * d3 * d3 : d3 - 0.5f);
}

// Parallel descending radix-select over NB bins; cnt may be global or shared.
__device__ __forceinline__ void scan_desc(const int* cnt, int R, int tid,
                                          int* s_w, unsigned* s_idx, int* s_rem,
                                          int* lc_out)
{
    int lane = tid & 31, w = tid >> 5;
    int base = tid * 8;
    int c = 0;
#pragma unroll
    for (int k = 0; k < 8; k++) { lc_out[k] = cnt[NB - 1 - (base + k)]; c += lc_out[k]; }
    int inc = c;
#pragma unroll
    for (int o = 1; o < 32; o <<= 1) {
        int n = __shfl_up_sync(0xFFFFFFFFu, inc, o);
        if (lane >= o) inc += n;
    }
    if (lane == 31) s_w[w] = inc;
    __syncthreads();
    if (tid == 0) {
        int rc = 0;
        for (int i = 0; i < 8; i++) { int v = s_w[i]; s_w[i] = rc; rc += v; }
    }
    __syncthreads();
    int epc = s_w[w] + inc - c;
    if (epc < R && R <= epc + c) {
        int rc = epc;
#pragma unroll
        for (int k = 0; k < 8; k++) {
            int idx = NB - 1 - (base + k);
            if (rc + lc_out[k] >= R) { *s_idx = (unsigned)idx; *s_rem = R - rc; break; }
            rc += lc_out[k];
        }
    }
    __syncthreads();
}

// ---------------- K0: zero accumulators (+ cell histogram) ----------------
__global__ void __launch_bounds__(256) k_zero() {
    int g = blockIdx.x * 256 + threadIdx.x;
    for (int i = g; i < BB * NB; i += 16384) {
        ((int*)g_h1c)[i] = 0;
        ((int*)g_h2c)[i] = 0;
        ((int*)g_h3c)[i] = 0;
    }
    if (g < 1024) g_chist[g] = 0;
    if (g < BB) { g_poscnt[g] = 0; g_posloss[g] = 0.0; g_sgt[g] = 0.0; }
    if (g == BB) { g_lossl = 0.0; g_ctr = 0; }
}

// ---------------- k_mh: max prior half extents + cell histogram ----------------
__global__ void __launch_bounds__(256) k_mh(const float4* __restrict__ priors) {
    __shared__ int sh[1024];
    int tid = threadIdx.x, lane = tid & 31;
    for (int i = tid; i < 1024; i += 256) sh[i] = 0;
    __syncthreads();
    int base = blockIdx.x * 1024;
    float hx = 0.0f, hy = 0.0f;
#pragma unroll
    for (int k = 0; k < 4; k++) {
        int p = base + k * 256 + tid;
        float4 pr = priors[p];
        hx = fmaxf(hx, pr.z);
        hy = fmaxf(hy, pr.w);
        atomicAdd(&sh[cell_of(pr)], 1);
    }
    hx = __fmul_rn(0.5f, hx);   // exact (×0.5)
    hy = __fmul_rn(0.5f, hy);
#pragma unroll
    for (int o = 16; o > 0; o >>= 1) {
        hx = fmaxf(hx, __shfl_down_sync(0xFFFFFFFFu, hx, o));
        hy = fmaxf(hy, __shfl_down_sync(0xFFFFFFFFu, hy, o));
    }
    if (lane == 0) {
        atomicMax(&g_mhx, __float_as_int(hx));
        atomicMax(&g_mhy, __float_as_int(hy));
    }
    __syncthreads();
    for (int i = tid; i < 1024; i += 256)
        if (sh[i]) atomicAdd(&g_chist[i], sh[i]);
}

// ---------------- kseed: seeds (warp-per-truth over SEEDN priors) + cell masks ----------------
__global__ void __launch_bounds__(256) kseed(const float4* __restrict__ priors,
                                             const float*  __restrict__ targets) {
    int b = blockIdx.x, half = blockIdx.y;
    int tid = threadIdx.x, w = tid >> 5, lane = tid & 31;
    __shared__ float4 str[TT];
    __shared__ float s_mhx, s_mhy;
    if (tid < TT) {
        const float* tb = targets + (b * TT + tid) * 5;
        str[tid] = make_float4(tb[0], tb[1], tb[2], tb[3]);
    }
    if (tid == 0) {
        s_mhx = __fadd_rn(__int_as_float(g_mhx), 1e-5f);
        s_mhy = __fadd_rn(__int_as_float(g_mhy), 1e-5f);
    }
    __syncthreads();

    float mhx = s_mhx, mhy = s_mhy;
    for (int c = tid; c < 512; c += 256) {
        int cell = half * 512 + c;
        int ci = cell & 31, cj = cell >> 5;
        float clx = ci * 0.03125f, chx = __fadd_rn(clx, 0.03125f);
        float cly = cj * 0.03125f, chy = __fadd_rn(cly, 0.03125f);
        unsigned m = 0;
#pragma unroll
        for (int t = 0; t < TT; t++) {
            float4 a = str[t];
            bool in = (__fsub_rn(a.x, mhx) <= chx) && (clx <= __fadd_rn(a.z, mhx))
                   && (__fsub_rn(a.y, mhy) <= chy) && (cly <= __fadd_rn(a.w, mhy));
            if (in) m |= (1u << t);
        }
        g_tmask[b][cell] = (unsigned short)m;
    }

    int t = half * 8 + w;
    float4 a = str[t];
    float ca = __fmul_rn(__fsub_rn(a.z, a.x), __fsub_rn(a.w, a.y));
    float bi = -1.0f, bd = 1.0f; unsigned bp = 0;
#pragma unroll 4
    for (int i = 0; i < SEEDN; i += 32) {
        int p = i + lane;
        Box bx = mkbox(priors[p]);
        float inter, den;
        iou_id(bx, a, ca, inter, den);
        if (__fmul_rn(inter, bd) > __fmul_rn(bi, den)) { bi = inter; bd = den; bp = p; }
    }
#pragma unroll
    for (int o = 16; o > 0; o >>= 1) {
        float oi = __shfl_down_sync(0xFFFFFFFFu, bi, o);
        float od = __shfl_down_sync(0xFFFFFFFFu, bd, o);
        unsigned op_ = __shfl_down_sync(0xFFFFFFFFu, bp, o);
        if (__fmul_rn(oi, bd) > __fmul_rn(bi, od)) { bi = oi; bd = od; bp = op_; }
    }
    if (lane == 0) {
        float iou = __fdiv_rn(bi, bd);
        g_skey[b][t] = ((unsigned long long)__float_as_uint(iou) << 32)
                     | (unsigned long long)(0xFFFFFFFFu - bp);   // exclusive owner
    }
}

// ---------------- k_scan_cells: exclusive scan of 1024-bin cell histogram ----------------
__global__ void __launch_bounds__(256) k_scan_cells() {
    __shared__ int sw[8];
    int tid = threadIdx.x, lane = tid & 31, w = tid >> 5;
    int v[4]; int s = 0;
#pragma unroll
    for (int k = 0; k < 4; k++) { v[k] = g_chist[tid * 4 + k]; s += v[k]; }
    int inc = s;
#pragma unroll
    for (int o = 1; o < 32; o <<= 1) {
        int n = __shfl_up_sync(0xFFFFFFFFu, inc, o);
        if (lane >= o) inc += n;
    }
    if (lane == 31) sw[w] = inc;
    __syncthreads();
    if (tid == 0) {
        int rc = 0;
        for (int i = 0; i < 8; i++) { int x = sw[i]; sw[i] = rc; rc += x; }
    }
    __syncthreads();
    int base = sw[w] + inc - s;
#pragma unroll
    for (int k = 0; k < 4; k++) { g_cfill[tid * 4 + k] = base; base += v[k]; }
}

// ---------------- k_scatter: counting-sort priors by cell ----------------
__global__ void __launch_bounds__(256) k_scatter(const float4* __restrict__ priors) {
    int base = blockIdx.x * 1024;
#pragma unroll
    for (int k = 0; k < 4; k++) {
        int p = base + k * 256 + threadIdx.x;
        float4 pr = priors[p];
        int pos = atomicAdd(&g_cfill[cell_of(pr)], 1);
        g_sp[pos] = pr;
        g_sidx[pos] = p;
    }
}

// ---------------- K1: cell-sorted mask-gated match + losses + level-1 histogram ----------------
__global__ void __launch_bounds__(BLK, 4) k1(const float4* __restrict__ loc,
                                             const float2* __restrict__ conf,
                                             const float*  __restrict__ targets) {
    int b = blockIdx.y, tid = threadIdx.x, lane = tid & 31;
    __shared__ float4 tr[TT];
    __shared__ float  cA[TT];
    __shared__ unsigned short smask[1024];
    __shared__ int    sc[NB];
    for (int i = tid; i < NB; i += BLK) sc[i] = 0;
    for (int i = tid; i < 512; i += BLK)
        ((unsigned*)smask)[i] = ((const unsigned*)g_tmask[b])[i];
    if (tid < TT) {
        const float* tb = targets + (b * TT + tid) * 5;
        float4 v = make_float4(tb[0], tb[1], tb[2], tb[3]);
        tr[tid] = v;
        cA[tid] = __fmul_rn(__fsub_rn(v.z, v.x), __fsub_rn(v.w, v.y));
    }
    __syncthreads();

    float c_min = 1e30f;
#pragma unroll
    for (int t = 0; t < TT; t++)
        c_min = fminf(c_min, __uint_as_float((unsigned)(g_skey[b][t] >> 32)));

    float lossl = 0.0f, ploss = 0.0f;
    int pcnt = 0;
    int pbase = blockIdx.x * (BLK * IPT);
#pragma unroll 1
    for (int i = 0; i < IPT; i++) {
        int j = pbase + i * BLK + tid;
        float4 pr = g_sp[j];
        int p = g_sidx[j];
        Box bx = mkbox(pr);
        unsigned mm = smask[cell_of(pr)];    // warp-uniform (sorted by cell)

        // masked argmax, divergent loop — near-zero divergence after sort.
        float bi = -1.0f, bd = 1.0f; int bti = 0;
        while (mm) {
            int t = __ffs(mm) - 1;
            mm &= (mm - 1u);
            float inter, den;
            iou_id(bx, tr[t], cA[t], inter, den);
            if (__fmul_rn(inter, bd) > __fmul_rn(bi, den)) {
                bi = inter; bd = den; bti = t;
            }
        }

        // cheap gate: can this prior beat ANY truth's current best?
        bool maybe = (__fmul_rn(bi, GMARGIN) >= __fmul_rn(c_min, bd));
        if (__any_sync(0xFFFFFFFFu, maybe)) {
#pragma unroll 1
            for (int t = 0; t < TT; t++) {
                float inter, den;
                iou_id(bx, tr[t], cA[t], inter, den);
                float ct = __uint_as_float((unsigned)(g_skey[b][t] >> 32));
                bool cand = maybe &&
                    (__fmul_rn(inter, GMARGIN) >= __fmul_rn(ct, den));
                if (__ballot_sync(0xFFFFFFFFu, cand)) {
                    float ci = cand ? inter : -1.0f;
                    float cd = cand ? den : 1.0f;
                    unsigned cp = (unsigned)p;
#pragma unroll
                    for (int o = 16; o > 0; o >>= 1) {
                        float oi = __shfl_down_sync(0xFFFFFFFFu, ci, o);
                        float od = __shfl_down_sync(0xFFFFFFFFu, cd, o);
                        unsigned op_ = __shfl_down_sync(0xFFFFFFFFu, cp, o);
                        if (__fmul_rn(oi, cd) > __fmul_rn(ci, od)) { ci = oi; cd = od; cp = op_; }
                    }
                    if (lane == 0 && ci >= 0.0f) {
                        float iou = __fdiv_rn(ci, cd);
                        unsigned long long key =
                            ((unsigned long long)__float_as_uint(iou) << 32) |
                            (unsigned long long)(0xFFFFFFFFu - cp);
                        atomicMax(&g_skey[b][t], key);
                    }
                }
            }
        }

        bool pos = (__fmul_rn(2.0f, bi) >= bd);
        float2 c = conf[(size_t)b * PP + p];
        float lse = lse2(c);
        float mv = pos ? 0.0f : __fsub_rn(lse, c.x);
        unsigned bits = __float_as_uint(mv);
        g_mine[b][p] = bits;
        unsigned bin = bits >> 21;
        unsigned peers = __match_any_sync(0xFFFFFFFFu, bin);
        if (lane == __ffs(peers) - 1) atomicAdd(&sc[bin], __popc(peers));
        if (pos) {
            pcnt++;
            ploss += __fsub_rn(lse, c.y);
            lossl += loc_sl1(loc[(size_t)b * PP + p], tr[bti], pr);
        }
    }

#pragma unroll
    for (int o = 16; o > 0; o >>= 1) {
        lossl += __shfl_down_sync(0xFFFFFFFFu, lossl, o);
        ploss += __shfl_down_sync(0xFFFFFFFFu, ploss, o);
        pcnt  += __shfl_down_sync(0xFFFFFFFFu, pcnt, o);
    }
    if (lane == 0) {
        if (lossl != 0.0f) atomicAdd(&g_lossl, (double)lossl);
        if (pcnt) {
            atomicAdd(&g_poscnt[b], pcnt);
            atomicAdd(&g_posloss[b], (double)ploss);
        }
    }
    __syncthreads();
    for (int i = tid; i < NB; i += BLK) {
        int cv = sc[i];
        if (cv) atomicAdd(&g_h1c[b][i], cv);
    }
}

// ---------------- K2: best-prior override fixup — thread per (b,t) ----------------
__global__ void __launch_bounds__(512) k_fix(const float4* __restrict__ loc,
                                             const float2* __restrict__ conf,
                                             const float4* __restrict__ priors,
                                             const float*  __restrict__ targets) {
    int tid = threadIdx.x;
    int b = tid >> 4, t = tid & 15;
    __shared__ float4   str[BB][TT];
    __shared__ float    scA[BB][TT];
    __shared__ unsigned sps[BB][TT];
    {
        const float* tb = targets + (b * TT + t) * 5;
        float4 v = make_float4(tb[0], tb[1], tb[2], tb[3]);
        str[b][t] = v;
        scA[b][t] = __fmul_rn(__fsub_rn(v.z, v.x), __fsub_rn(v.w, v.y));
        sps[b][t] = 0xFFFFFFFFu - (unsigned)(g_skey[b][t] & 0xFFFFFFFFull);
    }
    __syncthreads();

    unsigned p = sps[b][t];
    bool last = true;
#pragma unroll
    for (int t2 = 0; t2 < TT; t2++)
        if (t2 > t && sps[b][t2] == p) last = false;
    if (!last) return;                       // last write wins

    float4 pr = priors[p];
    Box bx = mkbox(pr);
    float bi, bd; int bti;
    match_idx(bx, str[b], scA[b], bi, bd, bti);
    bool pos_old = (__fmul_rn(2.0f, bi) >= bd);
    float2 c = conf[(size_t)b * PP + p];
    float lse = lse2(c);
    float4 ld = loc[(size_t)b * PP + p];
    float sl_new = loc_sl1(ld, str[b][t], pr);
    double dl = 0.0;
    if (pos_old) {
        if (bti != t) dl = (double)sl_new - (double)loc_sl1(ld, str[b][bti], pr);
    } else {
        dl = (double)sl_new;
        atomicAdd(&g_poscnt[b], 1);
        atomicAdd(&g_posloss[b], (double)__fsub_rn(lse, c.y));
        float mo = __fsub_rn(lse, c.x);      // bit-identical to k1's mv
        unsigned ob = __float_as_uint(mo) >> 21;
        atomicSub(&g_h1c[b][ob], 1);
        atomicAdd(&g_h1c[b][0], 1);
        g_mine[b][p] = 0u;
    }
    if (dl != 0.0) atomicAdd(&g_lossl, dl);
}

// ---------------- k_fa: in-block level-0 select + level-1 histogram ----------------
__global__ void __launch_bounds__(256) k_fa() {
    int b = blockIdx.y, tid = threadIdx.x;
    __shared__ int sc[NB];
    __shared__ int s_w[8];
    __shared__ unsigned s_idx;
    __shared__ int s_rem;
    for (int i = tid; i < NB; i += 256) sc[i] = 0;

    int k3 = 3 * g_poscnt[b];
    int R = (k3 < PP - 1) ? k3 : (PP - 1);
    int lc[8];
    scan_desc(g_h1c[b], R, tid, s_w, &s_idx, &s_rem, lc);
    unsigned pref = s_idx;

    const uint4* mp = (const uint4*)&g_mine[b][0];
    int base = blockIdx.x * (PP / 4 / NBLKF);
#pragma unroll 2
    for (int i = tid; i < PP / 4 / NBLKF; i += 256) {
        uint4 v = mp[base + i];
        if ((v.x >> 21) == pref) atomicAdd(&sc[(v.x >> 10) & 0x7FFu], 1);
        if ((v.y >> 21) == pref) atomicAdd(&sc[(v.y >> 10) & 0x7FFu], 1);
        if ((v.z >> 21) == pref) atomicAdd(&sc[(v.z >> 10) & 0x7FFu], 1);
        if ((v.w >> 21) == pref) atomicAdd(&sc[(v.w >> 10) & 0x7FFu], 1);
    }
    __syncthreads();
    for (int i = tid; i < NB; i += 256)
        if (sc[i]) atomicAdd(&g_h2c[b][i], sc[i]);
    if (tid == 0 && blockIdx.x == 0) { g_pref0[b] = pref; g_R1[b] = s_rem; }
}

// ---------------- k_fb: in-block level-1 select + level-2 hist + upper sum ----------------
__global__ void __launch_bounds__(256) k_fb() {
    int b = blockIdx.y, tid = threadIdx.x, lane = tid & 31;
    __shared__ int sc[NB];
    __shared__ int s_w[8];
    __shared__ unsigned s_idx;
    __shared__ int s_rem;
    for (int i = tid; i < NB; i += 256) sc[i] = 0;

    int lc[8];
    scan_desc(g_h2c[b], g_R1[b], tid, s_w, &s_idx, &s_rem, lc);
    unsigned pref22 = (g_pref0[b] << 11) | s_idx;

    double fsum = 0.0;
    const uint4* mp = (const uint4*)&g_mine[b][0];
    int base = blockIdx.x * (PP / 4 / NBLKF);
#pragma unroll 2
    for (int i = tid; i < PP / 4 / NBLKF; i += 256) {
        uint4 v = mp[base + i];
        unsigned t0 = v.x >> 10, t1 = v.y >> 10, t2 = v.z >> 10, t3 = v.w >> 10;
        if (t0 == pref22) atomicAdd(&sc[v.x & 0x3FFu], 1);
        else if (t0 > pref22) fsum += (double)__uint_as_float(v.x);
        if (t1 == pref22) atomicAdd(&sc[v.y & 0x3FFu], 1);
        else if (t1 > pref22) fsum += (double)__uint_as_float(v.y);
        if (t2 == pref22) atomicAdd(&sc[v.z & 0x3FFu], 1);
        else if (t2 > pref22) fsum += (double)__uint_as_float(v.z);
        if (t3 == pref22) atomicAdd(&sc[v.w & 0x3FFu], 1);
        else if (t3 > pref22) fsum += (double)__uint_as_float(v.w);
    }
    __syncthreads();
    for (int i = tid; i < NB; i += 256)
        if (sc[i]) atomicAdd(&g_h3c[b][i], sc[i]);
#pragma unroll
    for (int o = 16; o > 0; o >>= 1)
        fsum += __shfl_down_sync(0xFFFFFFFFu, fsum, o);
    if (lane == 0 && fsum != 0.0) atomicAdd(&g_sgt[b], fsum);
    if (tid == 0 && blockIdx.x == 0) { g_pref22[b] = pref22; g_R2[b] = s_rem; }
}

// ---------------- k_last: level-2 select + exact top-K sum + final combine ----------------
__global__ void __launch_bounds__(256) k_last(float* __restrict__ out) {
    int b = blockIdx.x, tid = threadIdx.x;
    __shared__ int s_w[8];
    __shared__ unsigned s_idx;
    __shared__ int s_rem;
    __shared__ double s_ws[8];
    __shared__ int s_last;

    int lc[8];
    scan_desc(g_h3c[b], g_R2[b], tid, s_w, &s_idx, &s_rem, lc);
    unsigned pref = g_pref22[b];
    unsigned idx3 = s_idx;
    int R3 = s_rem;

    double s = 0.0;
    int base = tid * 8;
#pragma unroll
    for (int k = 0; k < 8; k++) {
        unsigned idx = (unsigned)(NB - 1 - (base + k));
        if (idx > idx3 && lc[k])
            s += (double)lc[k] * (double)__uint_as_float((pref << 10) | idx);
    }
#pragma unroll
    for (int o = 16; o > 0; o >>= 1)
        s += __shfl_down_sync(0xFFFFFFFFu, s, o);
    if ((tid & 31) == 0) s_ws[tid >> 5] = s;
    __syncthreads();
    if (tid == 0) {
        double tot = 0.0;
        for (int w = 0; w < 8; w++) tot += s_ws[w];
        g_topsum[b] = g_sgt[b] + tot +
                      (double)R3 * (double)__uint_as_float((pref << 10) | idx3);
        __threadfence();
        int done = atomicAdd(&g_ctr, 1);
        s_last = (done == BB - 1) ? 1 : 0;
    }
    __syncthreads();
    if (s_last) {
        __threadfence();
        if (tid < 32) {
            int np = g_poscnt[tid];
            double lc2 = g_posloss[tid] + g_topsum[tid];
#pragma unroll
            for (int o = 16; o > 0; o >>= 1) {
                np  += __shfl_down_sync(0xFFFFFFFFu, np, o);
                lc2 += __shfl_down_sync(0xFFFFFFFFu, lc2, o);
            }
            if (tid == 0) {
                double N = (double)np;
                out[0] = (float)(g_lossl / N);
                out[1] = (float)(lc2 / N);
            }
        }
    }
}

// ---------------- launch ----------------
extern "C" void kernel_launch(void* const* d_in, const int* in_sizes, int n_in,
                              void* d_out, int out_size) {
    const float4* loc     = (const float4*)d_in[0];
    const float2* conf    = (const float2*)d_in[1];
    const float4* priors  = (const float4*)d_in[2];
    const float*  targets = (const float*)d_in[3];
    float* out = (float*)d_out;

    k_zero<<<64, 256>>>();                              // 1
    k_mh<<<64, 256>>>(priors);                          // 2
    dim3 gs(BB, 2);
    kseed<<<gs, 256>>>(priors, targets);                // 3
    k_scan_cells<<<1, 256>>>();                         // 4
    k_scatter<<<64, 256>>>(priors);                     // 5
    dim3 g1(NBLK, BB);
    k1<<<g1, BLK>>>(loc, conf, targets);                // 6
    k_fix<<<1, 512>>>(loc, conf, priors, targets);      // 7
    dim3 gf(NBLKF, BB);
    k_fa<<<gf, 256>>>();                                // 8
    k_fb<<<gf, 256>>>();                                // 9
    k_last<<<BB, 256>>>(out);                           // 10
}

// round 17
// speedup vs baseline: 2.1111x; 1.0147x over previous
#include <cuda_runtime.h>

#define BB 32
#define PP 65536
#define TT 16
#define NB 2048
#define BLK 256
#define IPT 16
#define NBLK (PP/(BLK*IPT))   // 16 blocks per batch in k1
#define NBLKF 32              // 32 blocks per batch in filters
#define SEEDN 8192
#define GMARGIN 1.000002f

// ---------------- device scratch ----------------
__device__ unsigned int       g_mine[BB][PP];   // indexed by SORTED position
__device__ unsigned long long g_skey[BB][TT];
__device__ unsigned short     g_tmask[BB][1024];
__device__ int    g_mhx;      // float bits of max prior half-width (idempotent)
__device__ int    g_mhy;
__device__ int    g_chist[1024];
__device__ int    g_cfill[1024];
__device__ float4 g_sp[PP];   // cell-sorted priors
__device__ int    g_sidx[PP]; // original index of sorted prior
__device__ int    g_inv[PP];  // sorted position of original index
__device__ int    g_h1c[BB][NB];
__device__ int    g_h2c[BB][NB];
__device__ int    g_h3c[BB][NB];
__device__ int    g_poscnt[BB];
__device__ double g_posloss[BB];
__device__ double g_lossl;
__device__ unsigned g_pref0[BB];
__device__ int    g_R1[BB];
__device__ unsigned g_pref22[BB];
__device__ int    g_R2[BB];
__device__ double g_sgt[BB];
__device__ double g_topsum[BB];
__device__ int    g_ctr;

// ---------------- helpers (bit-identical across kernels) ----------------
struct Box { float x0, y0, x1, y1, areaB; };

__device__ __forceinline__ Box mkbox(float4 pr) {
    Box b;
    float hx = __fmul_rn(0.5f, pr.z), hy = __fmul_rn(0.5f, pr.w);
    b.x0 = __fsub_rn(pr.x, hx); b.y0 = __fsub_rn(pr.y, hy);
    b.x1 = __fadd_rn(pr.x, hx); b.y1 = __fadd_rn(pr.y, hy);
    b.areaB = __fmul_rn(__fsub_rn(b.x1, b.x0), __fsub_rn(b.y1, b.y0));
    return b;
}

__device__ __forceinline__ int cell_of(float4 pr) {
    int cx = (int)__fmul_rn(pr.x, 32.0f);
    cx = min(max(cx, 0), 31);
    int cy = (int)__fmul_rn(pr.y, 32.0f);
    cy = min(max(cy, 0), 31);
    return (cy << 5) + cx;
}

__device__ __forceinline__ void iou_id(const Box& bx, float4 a, float ca,
                                       float& inter, float& den) {
    float w = fmaxf(__fsub_rn(fminf(a.z, bx.x1), fmaxf(a.x, bx.x0)), 0.0f);
    float h = fmaxf(__fsub_rn(fminf(a.w, bx.y1), fmaxf(a.y, bx.y0)), 0.0f);
    inter = __fmul_rn(w, h);
    den = __fsub_rn(__fadd_rn(ca, bx.areaB), inter);
}

// Full serial chain argmax (used off the hot path: k_fix).
__device__ __forceinline__ void match_idx(
    const Box& bx, const float4* tr, const float* cA,
    float& bi, float& bd, int& bti)
{
    bi = -1.0f; bd = 1.0f; bti = 0;
#pragma unroll
    for (int t = 0; t < TT; t++) {
        float inter, den;
        iou_id(bx, tr[t], cA[t], inter, den);
        if (__fmul_rn(inter, bd) > __fmul_rn(bi, den)) { bi = inter; bd = den; bti = t; }
    }
}

__device__ __forceinline__ float lse2(float2 c) {
    return __fadd_rn(fmaxf(c.x, c.y),
                     __logf(__fadd_rn(1.0f, __expf(-fabsf(__fsub_rn(c.x, c.y))))));
}

__device__ __forceinline__ float loc_sl1(float4 ld, float4 a, float4 pr) {
    float gx = ((a.x + a.z) * 0.5f - pr.x) / (0.1f * pr.z);
    float gy = ((a.y + a.w) * 0.5f - pr.y) / (0.1f * pr.w);
    float gw = __logf((a.z - a.x) / pr.z) / 0.2f;
    float gh = __logf((a.w - a.y) / pr.w) / 0.2f;
    float d0 = fabsf(ld.x - gx), d1 = fabsf(ld.y - gy);
    float d2 = fabsf(ld.z - gw), d3 = fabsf(ld.w - gh);
    return (d0 < 1.f ? 0.5f * d0 * d0 : d0 - 0.5f)
         + (d1 < 1.f ? 0.5f * d1 * d1 : d1 - 0.5f)
         + (d2 < 1.f ? 0.5f * d2 * d2 : d2 - 0.5f)
         + (d3 < 1.f ? 0.5f * d3 * d3 : d3 - 0.5f);
}

// Parallel descending radix-select over NB bins; cnt may be global or shared.
__device__ __forceinline__ void scan_desc(const int* cnt, int R, int tid,
                                          int* s_w, unsigned* s_idx, int* s_rem,
                                          int* lc_out)
{
    int lane = tid & 31, w = tid >> 5;
    int base = tid * 8;
    int c = 0;
#pragma unroll
    for (int k = 0; k < 8; k++) { lc_out[k] = cnt[NB - 1 - (base + k)]; c += lc_out[k]; }
    int inc = c;
#pragma unroll
    for (int o = 1; o < 32; o <<= 1) {
        int n = __shfl_up_sync(0xFFFFFFFFu, inc, o);
        if (lane >= o) inc += n;
    }
    if (lane == 31) s_w[w] = inc;
    __syncthreads();
    if (tid == 0) {
        int rc = 0;
        for (int i = 0; i < 8; i++) { int v = s_w[i]; s_w[i] = rc; rc += v; }
    }
    __syncthreads();
    int epc = s_w[w] + inc - c;
    if (epc < R && R <= epc + c) {
        int rc = epc;
#pragma unroll
        for (int k = 0; k < 8; k++) {
            int idx = NB - 1 - (base + k);
            if (rc + lc_out[k] >= R) { *s_idx = (unsigned)idx; *s_rem = R - rc; break; }
            rc += lc_out[k];
        }
    }
    __syncthreads();
}

// ---------------- K0: zero accumulators (+ cell histogram) ----------------
__global__ void __launch_bounds__(256) k_zero() {
    int g = blockIdx.x * 256 + threadIdx.x;
    for (int i = g; i < BB * NB; i += 16384) {
        ((int*)g_h1c)[i] = 0;
        ((int*)g_h2c)[i] = 0;
        ((int*)g_h3c)[i] = 0;
    }
    if (g < 1024) g_chist[g] = 0;
    if (g < BB) { g_poscnt[g] = 0; g_posloss[g] = 0.0; g_sgt[g] = 0.0; }
    if (g == BB) { g_lossl = 0.0; g_ctr = 0; }
}

// ---------------- k_mh: max prior half extents + cell histogram ----------------
__global__ void __launch_bounds__(256) k_mh(const float4* __restrict__ priors) {
    __shared__ int sh[1024];
    int tid = threadIdx.x, lane = tid & 31;
    for (int i = tid; i < 1024; i += 256) sh[i] = 0;
    __syncthreads();
    int base = blockIdx.x * 1024;
    float hx = 0.0f, hy = 0.0f;
#pragma unroll
    for (int k = 0; k < 4; k++) {
        int p = base + k * 256 + tid;
        float4 pr = priors[p];
        hx = fmaxf(hx, pr.z);
        hy = fmaxf(hy, pr.w);
        atomicAdd(&sh[cell_of(pr)], 1);
    }
    hx = __fmul_rn(0.5f, hx);   // exact (×0.5)
    hy = __fmul_rn(0.5f, hy);
#pragma unroll
    for (int o = 16; o > 0; o >>= 1) {
        hx = fmaxf(hx, __shfl_down_sync(0xFFFFFFFFu, hx, o));
        hy = fmaxf(hy, __shfl_down_sync(0xFFFFFFFFu, hy, o));
    }
    if (lane == 0) {
        atomicMax(&g_mhx, __float_as_int(hx));
        atomicMax(&g_mhy, __float_as_int(hy));
    }
    __syncthreads();
    for (int i = tid; i < 1024; i += 256)
        if (sh[i]) atomicAdd(&g_chist[i], sh[i]);
}

// ---------------- kseed: seeds + cell masks (+ cell scan in block (0,0)) ----------------
__global__ void __launch_bounds__(256) kseed(const float4* __restrict__ priors,
                                             const float*  __restrict__ targets) {
    int b = blockIdx.x, half = blockIdx.y;
    int tid = threadIdx.x, w = tid >> 5, lane = tid & 31;
    __shared__ float4 str[TT];
    __shared__ float s_mhx, s_mhy;
    __shared__ int sw[8];

    // block (0,0): exclusive scan of g_chist -> g_cfill (chist complete after k_mh)
    if (b == 0 && half == 0) {
        int v[4]; int s = 0;
#pragma unroll
        for (int k = 0; k < 4; k++) { v[k] = g_chist[tid * 4 + k]; s += v[k]; }
        int inc = s;
#pragma unroll
        for (int o = 1; o < 32; o <<= 1) {
            int n = __shfl_up_sync(0xFFFFFFFFu, inc, o);
            if (lane >= o) inc += n;
        }
        if (lane == 31) sw[w] = inc;
        __syncthreads();
        if (tid == 0) {
            int rc = 0;
            for (int i = 0; i < 8; i++) { int x = sw[i]; sw[i] = rc; rc += x; }
        }
        __syncthreads();
        int base = sw[w] + inc - s;
#pragma unroll
        for (int k = 0; k < 4; k++) { g_cfill[tid * 4 + k] = base; base += v[k]; }
    }

    if (tid < TT) {
        const float* tb = targets + (b * TT + tid) * 5;
        str[tid] = make_float4(tb[0], tb[1], tb[2], tb[3]);
    }
    if (tid == 0) {
        s_mhx = __fadd_rn(__int_as_float(g_mhx), 1e-5f);
        s_mhy = __fadd_rn(__int_as_float(g_mhy), 1e-5f);
    }
    __syncthreads();

    float mhx = s_mhx, mhy = s_mhy;
    for (int c = tid; c < 512; c += 256) {
        int cell = half * 512 + c;
        int ci = cell & 31, cj = cell >> 5;
        float clx = ci * 0.03125f, chx = __fadd_rn(clx, 0.03125f);
        float cly = cj * 0.03125f, chy = __fadd_rn(cly, 0.03125f);
        unsigned m = 0;
#pragma unroll
        for (int t = 0; t < TT; t++) {
            float4 a = str[t];
            bool in = (__fsub_rn(a.x, mhx) <= chx) && (clx <= __fadd_rn(a.z, mhx))
                   && (__fsub_rn(a.y, mhy) <= chy) && (cly <= __fadd_rn(a.w, mhy));
            if (in) m |= (1u << t);
        }
        g_tmask[b][cell] = (unsigned short)m;
    }

    int t = half * 8 + w;
    float4 a = str[t];
    float ca = __fmul_rn(__fsub_rn(a.z, a.x), __fsub_rn(a.w, a.y));
    float bi = -1.0f, bd = 1.0f; unsigned bp = 0;
#pragma unroll 4
    for (int i = 0; i < SEEDN; i += 32) {
        int p = i + lane;
        Box bx = mkbox(priors[p]);
        float inter, den;
        iou_id(bx, a, ca, inter, den);
        if (__fmul_rn(inter, bd) > __fmul_rn(bi, den)) { bi = inter; bd = den; bp = p; }
    }
#pragma unroll
    for (int o = 16; o > 0; o >>= 1) {
        float oi = __shfl_down_sync(0xFFFFFFFFu, bi, o);
        float od = __shfl_down_sync(0xFFFFFFFFu, bd, o);
        unsigned op_ = __shfl_down_sync(0xFFFFFFFFu, bp, o);
        if (__fmul_rn(oi, bd) > __fmul_rn(bi, od)) { bi = oi; bd = od; bp = op_; }
    }
    if (lane == 0) {
        float iou = __fdiv_rn(bi, bd);
        g_skey[b][t] = ((unsigned long long)__float_as_uint(iou) << 32)
                     | (unsigned long long)(0xFFFFFFFFu - bp);   // exclusive owner
    }
}

// ---------------- k_scatter: counting-sort priors by cell (+ inverse map) ----------------
__global__ void __launch_bounds__(256) k_scatter(const float4* __restrict__ priors) {
    int base = blockIdx.x * 1024;
#pragma unroll
    for (int k = 0; k < 4; k++) {
        int p = base + k * 256 + threadIdx.x;
        float4 pr = priors[p];
        int pos = atomicAdd(&g_cfill[cell_of(pr)], 1);
        g_sp[pos] = pr;
        g_sidx[pos] = p;
        g_inv[p] = pos;
    }
}

// ---------------- K1: cell-sorted mask-gated match + losses + level-1 histogram ----------------
__global__ void __launch_bounds__(BLK, 4) k1(const float4* __restrict__ loc,
                                             const float2* __restrict__ conf,
                                             const float*  __restrict__ targets) {
    int b = blockIdx.y, tid = threadIdx.x, lane = tid & 31;
    __shared__ float4 tr[TT];
    __shared__ float  cA[TT];
    __shared__ unsigned short smask[1024];
    __shared__ int    sc[NB];
    for (int i = tid; i < NB; i += BLK) sc[i] = 0;
    for (int i = tid; i < 512; i += BLK)
        ((unsigned*)smask)[i] = ((const unsigned*)g_tmask[b])[i];
    if (tid < TT) {
        const float* tb = targets + (b * TT + tid) * 5;
        float4 v = make_float4(tb[0], tb[1], tb[2], tb[3]);
        tr[tid] = v;
        cA[tid] = __fmul_rn(__fsub_rn(v.z, v.x), __fsub_rn(v.w, v.y));
    }
    __syncthreads();

    float c_min = 1e30f;
#pragma unroll
    for (int t = 0; t < TT; t++)
        c_min = fminf(c_min, __uint_as_float((unsigned)(g_skey[b][t] >> 32)));

    float lossl = 0.0f, ploss = 0.0f;
    int pcnt = 0;
    int pbase = blockIdx.x * (BLK * IPT);
#pragma unroll 1
    for (int i = 0; i < IPT; i++) {
        int j = pbase + i * BLK + tid;
        float4 pr = g_sp[j];
        int p = g_sidx[j];
        Box bx = mkbox(pr);
        unsigned mm = smask[cell_of(pr)];    // warp-uniform (sorted by cell)

        float bi = -1.0f, bd = 1.0f; int bti = 0;
        while (mm) {
            int t = __ffs(mm) - 1;
            mm &= (mm - 1u);
            float inter, den;
            iou_id(bx, tr[t], cA[t], inter, den);
            if (__fmul_rn(inter, bd) > __fmul_rn(bi, den)) {
                bi = inter; bd = den; bti = t;
            }
        }

        bool maybe = (__fmul_rn(bi, GMARGIN) >= __fmul_rn(c_min, bd));
        if (__any_sync(0xFFFFFFFFu, maybe)) {
#pragma unroll 1
            for (int t = 0; t < TT; t++) {
                float inter, den;
                iou_id(bx, tr[t], cA[t], inter, den);
                float ct = __uint_as_float((unsigned)(g_skey[b][t] >> 32));
                bool cand = maybe &&
                    (__fmul_rn(inter, GMARGIN) >= __fmul_rn(ct, den));
                if (__ballot_sync(0xFFFFFFFFu, cand)) {
                    float ci = cand ? inter : -1.0f;
                    float cd = cand ? den : 1.0f;
                    unsigned cp = (unsigned)p;
#pragma unroll
                    for (int o = 16; o > 0; o >>= 1) {
                        float oi = __shfl_down_sync(0xFFFFFFFFu, ci, o);
                        float od = __shfl_down_sync(0xFFFFFFFFu, cd, o);
                        unsigned op_ = __shfl_down_sync(0xFFFFFFFFu, cp, o);
                        if (__fmul_rn(oi, cd) > __fmul_rn(ci, od)) { ci = oi; cd = od; cp = op_; }
                    }
                    if (lane == 0 && ci >= 0.0f) {
                        float iou = __fdiv_rn(ci, cd);
                        unsigned long long key =
                            ((unsigned long long)__float_as_uint(iou) << 32) |
                            (unsigned long long)(0xFFFFFFFFu - cp);
                        atomicMax(&g_skey[b][t], key);
                    }
                }
            }
        }

        bool pos = (__fmul_rn(2.0f, bi) >= bd);
        float2 c = conf[(size_t)b * PP + p];
        float lse = lse2(c);
        float mv = pos ? 0.0f : __fsub_rn(lse, c.x);
        unsigned bits = __float_as_uint(mv);
        g_mine[b][j] = bits;                  // coalesced: sorted position
        unsigned bin = bits >> 21;
        unsigned peers = __match_any_sync(0xFFFFFFFFu, bin);
        if (lane == __ffs(peers) - 1) atomicAdd(&sc[bin], __popc(peers));
        if (pos) {
            pcnt++;
            ploss += __fsub_rn(lse, c.y);
            lossl += loc_sl1(loc[(size_t)b * PP + p], tr[bti], pr);
        }
    }

#pragma unroll
    for (int o = 16; o > 0; o >>= 1) {
        lossl += __shfl_down_sync(0xFFFFFFFFu, lossl, o);
        ploss += __shfl_down_sync(0xFFFFFFFFu, ploss, o);
        pcnt  += __shfl_down_sync(0xFFFFFFFFu, pcnt, o);
    }
    if (lane == 0) {
        if (lossl != 0.0f) atomicAdd(&g_lossl, (double)lossl);
        if (pcnt) {
            atomicAdd(&g_poscnt[b], pcnt);
            atomicAdd(&g_posloss[b], (double)ploss);
        }
    }
    __syncthreads();
    for (int i = tid; i < NB; i += BLK) {
        int cv = sc[i];
        if (cv) atomicAdd(&g_h1c[b][i], cv);
    }
}

// ---------------- K2: best-prior override fixup — thread per (b,t) ----------------
__global__ void __launch_bounds__(512) k_fix(const float4* __restrict__ loc,
                                             const float2* __restrict__ conf,
                                             const float4* __restrict__ priors,
                                             const float*  __restrict__ targets) {
    int tid = threadIdx.x;
    int b = tid >> 4, t = tid & 15;
    __shared__ float4   str[BB][TT];
    __shared__ float    scA[BB][TT];
    __shared__ unsigned sps[BB][TT];
    {
        const float* tb = targets + (b * TT + t) * 5;
        float4 v = make_float4(tb[0], tb[1], tb[2], tb[3]);
        str[b][t] = v;
        scA[b][t] = __fmul_rn(__fsub_rn(v.z, v.x), __fsub_rn(v.w, v.y));
        sps[b][t] = 0xFFFFFFFFu - (unsigned)(g_skey[b][t] & 0xFFFFFFFFull);
    }
    __syncthreads();

    unsigned p = sps[b][t];
    bool last = true;
#pragma unroll
    for (int t2 = 0; t2 < TT; t2++)
        if (t2 > t && sps[b][t2] == p) last = false;
    if (!last) return;                       // last write wins

    float4 pr = priors[p];
    Box bx = mkbox(pr);
    float bi, bd; int bti;
    match_idx(bx, str[b], scA[b], bi, bd, bti);
    bool pos_old = (__fmul_rn(2.0f, bi) >= bd);
    float2 c = conf[(size_t)b * PP + p];
    float lse = lse2(c);
    float4 ld = loc[(size_t)b * PP + p];
    float sl_new = loc_sl1(ld, str[b][t], pr);
    double dl = 0.0;
    if (pos_old) {
        if (bti != t) dl = (double)sl_new - (double)loc_sl1(ld, str[b][bti], pr);
    } else {
        dl = (double)sl_new;
        atomicAdd(&g_poscnt[b], 1);
        atomicAdd(&g_posloss[b], (double)__fsub_rn(lse, c.y));
        float mo = __fsub_rn(lse, c.x);      // bit-identical to k1's mv
        unsigned ob = __float_as_uint(mo) >> 21;
        atomicSub(&g_h1c[b][ob], 1);
        atomicAdd(&g_h1c[b][0], 1);
        g_mine[b][g_inv[p]] = 0u;
    }
    if (dl != 0.0) atomicAdd(&g_lossl, dl);
}

// ---------------- k_fa: in-block level-0 select + level-1 histogram ----------------
__global__ void __launch_bounds__(256) k_fa() {
    int b = blockIdx.y, tid = threadIdx.x;
    __shared__ int sc[NB];
    __shared__ int s_w[8];
    __shared__ unsigned s_idx;
    __shared__ int s_rem;
    for (int i = tid; i < NB; i += 256) sc[i] = 0;

    int k3 = 3 * g_poscnt[b];
    int R = (k3 < PP - 1) ? k3 : (PP - 1);
    int lc[8];
    scan_desc(g_h1c[b], R, tid, s_w, &s_idx, &s_rem, lc);
    unsigned pref = s_idx;

    const uint4* mp = (const uint4*)&g_mine[b][0];
    int base = blockIdx.x * (PP / 4 / NBLKF);
#pragma unroll 2
    for (int i = tid; i < PP / 4 / NBLKF; i += 256) {
        uint4 v = mp[base + i];
        if ((v.x >> 21) == pref) atomicAdd(&sc[(v.x >> 10) & 0x7FFu], 1);
        if ((v.y >> 21) == pref) atomicAdd(&sc[(v.y >> 10) & 0x7FFu], 1);
        if ((v.z >> 21) == pref) atomicAdd(&sc[(v.z >> 10) & 0x7FFu], 1);
        if ((v.w >> 21) == pref) atomicAdd(&sc[(v.w >> 10) & 0x7FFu], 1);
    }
    __syncthreads();
    for (int i = tid; i < NB; i += 256)
        if (sc[i]) atomicAdd(&g_h2c[b][i], sc[i]);
    if (tid == 0 && blockIdx.x == 0) { g_pref0[b] = pref; g_R1[b] = s_rem; }
}

// ---------------- k_fb: in-block level-1 select + level-2 hist + upper sum ----------------
__global__ void __launch_bounds__(256) k_fb() {
    int b = blockIdx.y, tid = threadIdx.x, lane = tid & 31;
    __shared__ int sc[NB];
    __shared__ int s_w[8];
    __shared__ unsigned s_idx;
    __shared__ int s_rem;
    for (int i = tid; i < NB; i += 256) sc[i] = 0;

    int lc[8];
    scan_desc(g_h2c[b], g_R1[b], tid, s_w, &s_idx, &s_rem, lc);
    unsigned pref22 = (g_pref0[b] << 11) | s_idx;

    double fsum = 0.0;
    const uint4* mp = (const uint4*)&g_mine[b][0];
    int base = blockIdx.x * (PP / 4 / NBLKF);
#pragma unroll 2
    for (int i = tid; i < PP / 4 / NBLKF; i += 256) {
        uint4 v = mp[base + i];
        unsigned t0 = v.x >> 10, t1 = v.y >> 10, t2 = v.z >> 10, t3 = v.w >> 10;
        if (t0 == pref22) atomicAdd(&sc[v.x & 0x3FFu], 1);
        else if (t0 > pref22) fsum += (double)__uint_as_float(v.x);
        if (t1 == pref22) atomicAdd(&sc[v.y & 0x3FFu], 1);
        else if (t1 > pref22) fsum += (double)__uint_as_float(v.y);
        if (t2 == pref22) atomicAdd(&sc[v.z & 0x3FFu], 1);
        else if (t2 > pref22) fsum += (double)__uint_as_float(v.z);
        if (t3 == pref22) atomicAdd(&sc[v.w & 0x3FFu], 1);
        else if (t3 > pref22) fsum += (double)__uint_as_float(v.w);
    }
    __syncthreads();
    for (int i = tid; i < NB; i += 256)
        if (sc[i]) atomicAdd(&g_h3c[b][i], sc[i]);
#pragma unroll
    for (int o = 16; o > 0; o >>= 1)
        fsum += __shfl_down_sync(0xFFFFFFFFu, fsum, o);
    if (lane == 0 && fsum != 0.0) atomicAdd(&g_sgt[b], fsum);
    if (tid == 0 && blockIdx.x == 0) { g_pref22[b] = pref22; g_R2[b] = s_rem; }
}

// ---------------- k_last: level-2 select + exact top-K sum + final combine ----------------
__global__ void __launch_bounds__(256) k_last(float* __restrict__ out) {
    int b = blockIdx.x, tid = threadIdx.x;
    __shared__ int s_w[8];
    __shared__ unsigned s_idx;
    __shared__ int s_rem;
    __shared__ double s_ws[8];
    __shared__ int s_last;

    int lc[8];
    scan_desc(g_h3c[b], g_R2[b], tid, s_w, &s_idx, &s_rem, lc);
    unsigned pref = g_pref22[b];
    unsigned idx3 = s_idx;
    int R3 = s_rem;

    double s = 0.0;
    int base = tid * 8;
#pragma unroll
    for (int k = 0; k < 8; k++) {
        unsigned idx = (unsigned)(NB - 1 - (base + k));
        if (idx > idx3 && lc[k])
            s += (double)lc[k] * (double)__uint_as_float((pref << 10) | idx);
    }
#pragma unroll
    for (int o = 16; o > 0; o >>= 1)
        s += __shfl_down_sync(0xFFFFFFFFu, s, o);
    if ((tid & 31) == 0) s_ws[tid >> 5] = s;
    __syncthreads();
    if (tid == 0) {
        double tot = 0.0;
        for (int w = 0; w < 8; w++) tot += s_ws[w];
        g_topsum[b] = g_sgt[b] + tot +
                      (double)R3 * (double)__uint_as_float((pref << 10) | idx3);
        __threadfence();
        int done = atomicAdd(&g_ctr, 1);
        s_last = (done == BB - 1) ? 1 : 0;
    }
    __syncthreads();
    if (s_last) {
        __threadfence();
        if (tid < 32) {
            int np = g_poscnt[tid];
            double lc2 = g_posloss[tid] + g_topsum[tid];
#pragma unroll
            for (int o = 16; o > 0; o >>= 1) {
                np  += __shfl_down_sync(0xFFFFFFFFu, np, o);
                lc2 += __shfl_down_sync(0xFFFFFFFFu, lc2, o);
            }
            if (tid == 0) {
                double N = (double)np;
                out[0] = (float)(g_lossl / N);
                out[1] = (float)(lc2 / N);
            }
        }
    }
}

// ---------------- launch ----------------
extern "C" void kernel_launch(void* const* d_in, const int* in_sizes, int n_in,
                              void* d_out, int out_size) {
    const float4* loc     = (const float4*)d_in[0];
    const float2* conf    = (const float2*)d_in[1];
    const float4* priors  = (const float4*)d_in[2];
    const float*  targets = (const float*)d_in[3];
    float* out = (float*)d_out;

    k_zero<<<64, 256>>>();                              // 1
    k_mh<<<64, 256>>>(priors);                          // 2
    dim3 gs(BB, 2);
    kseed<<<gs, 256>>>(priors, targets);                // 3 (includes cell scan)
    k_scatter<<<64, 256>>>(priors);                     // 4
    dim3 g1(NBLK, BB);
    k1<<<g1, BLK>>>(loc, conf, targets);                // 5
    k_fix<<<1, 512>>>(loc, conf, priors, targets);      // 6
    dim3 gf(NBLKF, BB);
    k_fa<<<gf, 256>>>();                                // 7
    k_fb<<<gf, 256>>>();                                // 8
    k_last<<<BB, 256>>>(out);                           // 9
}